// round 14
// baseline (speedup 1.0000x reference)
#include <cuda_runtime.h>
#include <cuda_bf16.h>
#include <mma.h>
#include <cstdint>

using namespace nvcuda;

constexpr int NB = 512;   // batch B
constexpr int ND = 768;   // D
constexpr int NH = 256;   // H
constexpr int NQ = 128;   // n = B/4
constexpr int NM = 256;   // m = B/2
constexpr float TAU_INV = 2.0f;
constexpr float PCOUNT = 57280.0f;

// ---------------- scratch ----------------
__device__ __nv_bfloat16 g_zh[NB * ND];
__device__ __nv_bfloat16 g_W1h[NH * 2 * ND];
__device__ __nv_bfloat16 g_W2h[NH * NH];
__device__ float g_A[NQ * NH];
__device__ __nv_bfloat16 g_Bfh[NB * NH];
__device__ float g_denomp[NQ * 8];
__device__ float g_pairp[NQ * 8];
__device__ float g_bcep[128];
__device__ unsigned g_ctr;

// ================= kernel A: norm (bx<128) | W1/W2 convert (MLP=4) ========
__global__ void k_prep(const float* __restrict__ x,
                       const float* __restrict__ W1, const float* __restrict__ W2) {
    int bx = blockIdx.x;
    if (bx == 0 && threadIdx.x == 0) g_ctr = 0;
    if (bx < 128) {
        __shared__ float sm[8];
        const int w = threadIdx.x >> 5, lane = threadIdx.x & 31;
        const int r = bx * 4 + (w >> 1);
        const int hoff = (w & 1) * 384;
        const float* xr = x + r * ND;
        float s = 0.f;
#pragma unroll
        for (int q = 0; q < 12; q++) { float v = xr[hoff + lane + q * 32]; s += v * v; }
#pragma unroll
        for (int o = 16; o; o >>= 1) s += __shfl_down_sync(0xffffffffu, s, o);
        if (lane == 0) sm[w] = s;
        __syncthreads();
        float inv = 1.0f / fmaxf(sqrtf(sm[w & ~1] + sm[(w & ~1) + 1]), 1e-12f);
        const int poff = (w & 1) * 192;
#pragma unroll
        for (int q = 0; q < 6; q++) {
            int p = poff + lane + q * 32;
            __nv_bfloat162 v = __floats2bfloat162_rn(xr[2 * p] * inv, xr[2 * p + 1] * inv);
            *reinterpret_cast<__nv_bfloat162*>(g_zh + r * ND + 2 * p) = v;
        }
    } else {
        // 112 blocks x 256 threads x 4 float4 = 458752 elements (W1 393216 + W2 65536)
        const int N1 = NH * 2 * ND;
        int base = (bx - 128) * 4096 + threadIdx.x * 4;
#pragma unroll
        for (int q = 0; q < 4; q++) {
            int off = base + q * 1024;
            const float* src;
            __nv_bfloat16* dst;
            int o;
            if (off < N1) { src = W1; dst = g_W1h; o = off; }
            else          { src = W2; dst = g_W2h; o = off - N1; }
            float4 v = *reinterpret_cast<const float4*>(src + o);
            *reinterpret_cast<__nv_bfloat162*>(dst + o)     = __floats2bfloat162_rn(v.x, v.y);
            *reinterpret_cast<__nv_bfloat162*>(dst + o + 2) = __floats2bfloat162_rn(v.z, v.w);
        }
    }
}

// ================= kernel B: featw-split (bx<80) | contrast (bx>=80) =======
constexpr int LZA = 776;
constexpr int LZB = 776;
constexpr int LSS = 68;
constexpr int B_ZB = 16 * LZA * 2;                 // 24832
constexpr int B_S0 = B_ZB + 64 * LZB * 2;          // 124160
constexpr int B_S1 = B_S0 + 16 * LSS * 4;          // 128512
constexpr int B_SMEM = B_S1 + 16 * LSS * 4;        // 132864

__global__ void __launch_bounds__(256, 1) k_mid() {
    extern __shared__ __align__(16) char dyn[];
    __nv_bfloat16* za = reinterpret_cast<__nv_bfloat16*>(dyn);
    const int tid = threadIdx.x;
    const int w = tid >> 5, lane = tid & 31;

    if (blockIdx.x < 80) {
        const int t = blockIdx.x;
        const bool isA = t < 16;
        const int rbase = (isA ? (t >> 1) : ((t - 16) >> 1)) * 16;
        const int colh = t & 1;
        const int off = isA ? 0 : ND;

        for (int c = tid; c < 16 * (ND / 8); c += 256) {
            int r = c / (ND / 8), d8 = c % (ND / 8);
            *reinterpret_cast<uint4*>(za + r * LZA + d8 * 8) =
                *reinterpret_cast<const uint4*>(g_zh + (rbase + r) * ND + d8 * 8);
        }
        __syncthreads();

        const int h = colh * 128 + w * 16;
        wmma::fragment<wmma::accumulator, 16, 16, 16, float> ce, co;
        wmma::fill_fragment(ce, 0.f);
        wmma::fill_fragment(co, 0.f);
#pragma unroll 4
        for (int kc = 0; kc < ND / 16; kc += 2) {
            wmma::fragment<wmma::matrix_a, 16, 16, 16, __nv_bfloat16, wmma::row_major> ae, ao;
            wmma::fragment<wmma::matrix_b, 16, 16, 16, __nv_bfloat16, wmma::col_major> be, bo;
            wmma::load_matrix_sync(ae, za + kc * 16, LZA);
            wmma::load_matrix_sync(ao, za + (kc + 1) * 16, LZA);
            wmma::load_matrix_sync(be, g_W1h + h * (2 * ND) + off + kc * 16, 2 * ND);
            wmma::load_matrix_sync(bo, g_W1h + h * (2 * ND) + off + (kc + 1) * 16, 2 * ND);
            wmma::mma_sync(ce, ae, be, ce);
            wmma::mma_sync(co, ao, bo, co);
        }
#pragma unroll
        for (int e = 0; e < ce.num_elements; e++) ce.x[e] += co.x[e];

        if (isA) {
            wmma::store_matrix_sync(g_A + rbase * NH + h, ce, NH, wmma::mem_row_major);
        } else {
            float* cbuf = reinterpret_cast<float*>(dyn);
            __syncthreads();
            wmma::store_matrix_sync(cbuf + w * 16, ce, 132, wmma::mem_row_major);
            __syncthreads();
            for (int c = tid; c < 16 * 64; c += 256) {
                int r = c >> 6, p = c & 63;
                __nv_bfloat162 v = __floats2bfloat162_rn(cbuf[r * 132 + 2 * p],
                                                         cbuf[r * 132 + 2 * p + 1]);
                *reinterpret_cast<__nv_bfloat162*>(g_Bfh + (rbase + r) * NH + colh * 128 + 2 * p) = v;
            }
        }
    } else {
        const int vb = blockIdx.x - 80;
        const int bx = vb >> 3;
        const int by = vb & 7;
        const int ibase = bx * 16;
        const int kbase = by * 64;

        __nv_bfloat16* zb = reinterpret_cast<__nv_bfloat16*>(dyn + B_ZB);
        float* S0 = reinterpret_cast<float*>(dyn + B_S0);
        float* S1 = reinterpret_cast<float*>(dyn + B_S1);

        for (int c = tid; c < 16 * (ND / 8); c += 256) {
            int r = c / (ND / 8), d8 = c % (ND / 8);
            *reinterpret_cast<uint4*>(za + r * LZA + d8 * 8) =
                *reinterpret_cast<const uint4*>(g_zh + (ibase + r) * ND + d8 * 8);
        }
        for (int c = tid; c < 64 * (ND / 8); c += 256) {
            int r = c / (ND / 8), d8 = c % (ND / 8);
            *reinterpret_cast<uint4*>(zb + r * LZB + d8 * 8) =
                *reinterpret_cast<const uint4*>(g_zh + (kbase + r) * ND + d8 * 8);
        }
        __syncthreads();

        const int wn = w & 3;
        const int wd = w >> 2;
        const int kcol = wn * 16;
        const int d0 = wd * 384;

        wmma::fragment<wmma::accumulator, 16, 16, 16, float> cf0, cf1;
        wmma::fill_fragment(cf0, 0.f);
        wmma::fill_fragment(cf1, 0.f);
#pragma unroll 4
        for (int kc = 0; kc < 24; kc += 2) {
            wmma::fragment<wmma::matrix_a, 16, 16, 16, __nv_bfloat16, wmma::row_major> a0, a1;
            wmma::fragment<wmma::matrix_b, 16, 16, 16, __nv_bfloat16, wmma::col_major> b0, b1;
            wmma::load_matrix_sync(a0, za + d0 + kc * 16, LZA);
            wmma::load_matrix_sync(b0, zb + kcol * LZB + d0 + kc * 16, LZB);
            wmma::load_matrix_sync(a1, za + d0 + (kc + 1) * 16, LZA);
            wmma::load_matrix_sync(b1, zb + kcol * LZB + d0 + (kc + 1) * 16, LZB);
            wmma::mma_sync(cf0, a0, b0, cf0);
            wmma::mma_sync(cf1, a1, b1, cf1);
        }
#pragma unroll
        for (int e = 0; e < cf0.num_elements; e++) cf0.x[e] += cf1.x[e];
        wmma::store_matrix_sync((wd ? S1 : S0) + kcol, cf0, LSS, wmma::mem_row_major);
        __syncthreads();

#pragma unroll
        for (int rr = 2 * w; rr <= 2 * w + 1; rr++) {
            int i = ibase + rr;
            float dacc = 0.f, pacc = 0.f;
#pragma unroll
            for (int cc = 0; cc < 2; cc++) {
                int c = lane + cc * 32;
                int k = kbase + c;
                float s = S0[rr * LSS + c] + S1[rr * LSS + c];
                if (k != i) dacc += expf(TAU_INV * s);
                if (k > i && k < NQ) pacc += s;
            }
#pragma unroll
            for (int o = 16; o; o >>= 1) {
                dacc += __shfl_down_sync(0xffffffffu, dacc, o);
                pacc += __shfl_down_sync(0xffffffffu, pacc, o);
            }
            if (lane == 0) {
                g_denomp[i * 8 + by] = dacc;
                g_pairp[i * 8 + by] = pacc;
            }
        }
    }
}

// ================= kernel C: pair MLP (tcgen05, warp-specialized) ==========
constexpr int U_SZ  = 196608;
constexpr int P_ASH = U_SZ;                 // 2048
constexpr int P_B2S = P_ASH + 2048;         // 1024
constexpr int P_W3S = P_B2S + 1024;         // 1024
constexpr int P_RR  = P_W3S + 1024;         // 1024
constexpr int P_RED = P_RR + 1024;          // 512 (128 floats)
constexpr int P_TM  = P_RED + 512;          // 16
constexpr int P_MB  = P_TM + 16;            // 32 (two mbarriers)
constexpr int P_SMEM = P_MB + 32;           // 202272 + pad

#if defined(__CUDA_ARCH_FEAT_SM103_ALL)
__device__ __forceinline__ uint32_t smem_u32(const void* p) {
    uint32_t a;
    asm("{ .reg .u64 t; cvta.to.shared.u64 t, %1; cvt.u32.u64 %0, t; }" : "=r"(a) : "l"(p));
    return a;
}
__device__ __forceinline__ uint32_t elect_one() {
    uint32_t p;
    asm volatile("{\n\t.reg .pred p;\n\telect.sync _|p, 0xFFFFFFFF;\n\tselp.b32 %0, 1, 0, p;\n\t}" : "=r"(p));
    return p;
}
#define MBAR_INIT(a, n) asm volatile("mbarrier.init.shared.b64 [%0], %1;" :: "r"(a), "r"(n) : "memory")
#define MBAR_WAIT(a, ph) do { \
    uint32_t _m = (a), _p = (ph), _d; \
    asm volatile("{\n\t.reg .pred p;\n\tmbarrier.try_wait.parity.acquire.cta.shared::cta.b64 p, [%1], %2;\n\tselp.b32 %0, 1, 0, p;\n\t}" \
        : "=r"(_d) : "r"(_m), "r"(_p) : "memory"); \
    if (!_d) { \
        asm volatile("{\n\t.reg .pred P1;\n\tWL_%=:\n\tmbarrier.try_wait.parity.acquire.cta.shared::cta.b64 P1, [%0], %1, 0x989680;\n\t@P1 bra.uni WD_%=;\n\tbra.uni WL_%=;\n\tWD_%=:\n\t}" \
            :: "r"(_m), "r"(_p) : "memory"); \
    } } while (0)
#define TC_ALLOC(sa, n)  asm volatile("tcgen05.alloc.cta_group::1.sync.aligned.shared::cta.b32 [%0], %1;" :: "r"(sa), "r"(n) : "memory")
#define TC_RELINQ()      asm volatile("tcgen05.relinquish_alloc_permit.cta_group::1.sync.aligned;")
#define TC_DEALLOC(t, n) asm volatile("tcgen05.dealloc.cta_group::1.sync.aligned.b32 %0, %1;" :: "r"(t), "r"(n))
#define TC_COMMIT(mb)    asm volatile("tcgen05.commit.cta_group::1.mbarrier::arrive::one.shared::cluster.b64 [%0];" :: "r"(mb) : "memory")
#define TC_WAIT_LD()     asm volatile("tcgen05.wait::ld.sync.aligned;" ::: "memory")
#define TC_FENCE_AFTER() asm volatile("tcgen05.fence::after_thread_sync;" ::: "memory")
#define TC_FENCE_BEFORE() asm volatile("tcgen05.fence::before_thread_sync;" ::: "memory")
#define FENCE_ASYNC()    asm volatile("fence.proxy.async.shared::cta;" ::: "memory")
#define TC_LD_X32(r, ta) \
    asm volatile("tcgen05.ld.sync.aligned.32x32b.x32.b32 " \
        "{%0, %1, %2, %3, %4, %5, %6, %7, %8, %9, %10, %11, %12, %13, %14, %15, " \
        " %16, %17, %18, %19, %20, %21, %22, %23, %24, %25, %26, %27, %28, %29, %30, %31}, [%32];" \
        : "=r"((r)[0]), "=r"((r)[1]), "=r"((r)[2]), "=r"((r)[3]), \
          "=r"((r)[4]), "=r"((r)[5]), "=r"((r)[6]), "=r"((r)[7]), \
          "=r"((r)[8]), "=r"((r)[9]), "=r"((r)[10]), "=r"((r)[11]), \
          "=r"((r)[12]), "=r"((r)[13]), "=r"((r)[14]), "=r"((r)[15]), \
          "=r"((r)[16]), "=r"((r)[17]), "=r"((r)[18]), "=r"((r)[19]), \
          "=r"((r)[20]), "=r"((r)[21]), "=r"((r)[22]), "=r"((r)[23]), \
          "=r"((r)[24]), "=r"((r)[25]), "=r"((r)[26]), "=r"((r)[27]), \
          "=r"((r)[28]), "=r"((r)[29]), "=r"((r)[30]), "=r"((r)[31]) \
        : "r"(ta))
__device__ __forceinline__ void mma_f16_ss_cg1(uint32_t d, uint64_t a, uint64_t b,
                                               uint32_t idesc, bool acc) {
    uint32_t en = acc ? 1u : 0u, zero = 0u;
    asm volatile(
        "{\n\t.reg .pred p;\n\tsetp.ne.u32 p, %5, 0;\n\t"
        "tcgen05.mma.cta_group::1.kind::f16 [%0], %1, %2, %3, {%4, %4, %4, %4}, p;\n\t}"
        :: "r"(d), "l"(a), "l"(b), "r"(idesc), "r"(zero), "r"(en) : "memory");
}
__device__ __forceinline__ uint64_t make_desc(uint32_t addr) {
    const uint64_t base = (uint64_t(2) << 61) | (uint64_t(1) << 46)
                        | (uint64_t(64) << 32) | (uint64_t(1) << 16);
    return base | ((uint64_t)(addr >> 4) & 0x3FFF);
}
__device__ __forceinline__ uint32_t sw128(uint32_t x) { return x ^ ((x >> 3) & 0x70); }
// N=128 half-GEMM idesc: f32 accum, bf16 x bf16, N=128, M=128
constexpr uint32_t IDESC_HALF = (1u << 4) | (1u << 7) | (1u << 10)
                              | (16u << 17) | (8u << 24);
#endif

__global__ void __launch_bounds__(256, 1)
k_pair(const float* __restrict__ b1, const float* __restrict__ b2,
       const float* __restrict__ w3, const float* __restrict__ b3v,
       float* __restrict__ out) {
    extern __shared__ __align__(16) char dyn[];
    __nv_bfloat16* ashh = reinterpret_cast<__nv_bfloat16*>(dyn + P_ASH);
    float* b2s = reinterpret_cast<float*>(dyn + P_B2S);
    float* w3s = reinterpret_cast<float*>(dyn + P_W3S);
    float* rr  = reinterpret_cast<float*>(dyn + P_RR);

    const int ibase = blockIdx.x * 4;
    const int j0 = blockIdx.y * 128;
    const int tid = threadIdx.x;
    const int w = tid >> 5, lane = tid & 31;
    const __nv_bfloat162 zero2 = __floats2bfloat162_rn(0.f, 0.f);
    float bacc = 0.f;

    {
        int h = tid;
        float bb = b1[h];
#pragma unroll
        for (int ii = 0; ii < 4; ii++)
            ashh[ii * 256 + h] = __float2bfloat16(g_A[(ibase + ii) * NH + h] + bb);
        b2s[h] = b2[h];
        w3s[h] = w3[h];
    }

#if defined(__CUDA_ARCH_FEAT_SM103_ALL)
    // ============== tcgen05 path: warp-specialized epilogue/fill ===========
    char* w2s = dyn;                 // swizzled W2, 131072 B
    char* h1s = dyn + 131072;        // swizzled h1, 65536 B
    float* red = reinterpret_cast<float*>(dyn + P_RED);   // [128]
    const uint32_t sbase = smem_u32(dyn);

    if (w == 0) { TC_ALLOC(sbase + P_TM, NH); TC_RELINQ(); }
    if (tid == 0) {
        MBAR_INIT(sbase + P_MB, 1);
        MBAR_INIT(sbase + P_MB + 8, 1);
    }

    for (int c = tid; c < 256 * 32; c += 256) {
        int n = c >> 5, g = c & 31;
        uint32_t off = (uint32_t)((n >> 3) * 1024 + (g >> 3) * 32768
                                + (n & 7) * 128 + (g & 7) * 16);
        *reinterpret_cast<uint4*>(w2s + sw128(off)) =
            *reinterpret_cast<const uint4*>(g_W2h + n * NH + g * 8);
    }

    // fill h1(0): all 256 threads
    {
        const __nv_bfloat16* ai = ashh;
        for (int c = tid; c < 128 * 32; c += 256) {
            int j = c >> 5, g = c & 31;
            uint4 bv = *reinterpret_cast<const uint4*>(g_Bfh + (j0 + j) * NH + g * 8);
            const __nv_bfloat162* ap = reinterpret_cast<const __nv_bfloat162*>(ai + g * 8);
            __nv_bfloat162* hv = reinterpret_cast<__nv_bfloat162*>(&bv);
#pragma unroll
            for (int q = 0; q < 4; q++) hv[q] = __hmax2(__hadd2(hv[q], ap[q]), zero2);
            uint32_t off = (uint32_t)((j >> 3) * 1024 + (g >> 3) * 16384
                                    + (j & 7) * 128 + (g & 7) * 16);
            *reinterpret_cast<uint4*>(h1s + sw128(off)) = bv;
        }
    }
    __syncthreads();

    uint32_t tmem;
    asm volatile("ld.shared.b32 %0, [%1];" : "=r"(tmem) : "r"(sbase + P_TM));

    const uint64_t a_base = make_desc(sbase + 131072);
    const uint64_t b_base = make_desc(sbase);

    for (int ii = 0; ii < 4; ii++) {
        const int i = ibase + ii;
        FENCE_ASYNC();
        __syncthreads();   // h1(ii) writes visible

        if (w == 0) {
            if (elect_one()) {
#pragma unroll
                for (int ks = 0; ks < 16; ks++) {
                    uint64_t ad = a_base + (uint64_t)((ks >> 2) * 1024 + (ks & 3) * 2);
                    uint64_t bd = b_base + (uint64_t)((ks >> 2) * 2048 + (ks & 3) * 2);
                    mma_f16_ss_cg1(tmem, ad, bd, IDESC_HALF, ks > 0);
                }
                TC_COMMIT(sbase + P_MB);
#pragma unroll
                for (int ks = 0; ks < 16; ks++) {
                    uint64_t ad = a_base + (uint64_t)((ks >> 2) * 1024 + (ks & 3) * 2);
                    uint64_t bd = b_base + 1024 + (uint64_t)((ks >> 2) * 2048 + (ks & 3) * 2);
                    mma_f16_ss_cg1(tmem + 128, ad, bd, IDESC_HALF, ks > 0);
                }
                TC_COMMIT(sbase + P_MB + 8);
            }
        }

        if (w < 4) {
            // consumer warps: full epilogue, warp w = subpartition w = rows w*32+lane
            float s = 0.f;
            MBAR_WAIT(sbase + P_MB, ii & 1);
            TC_FENCE_AFTER();
#pragma unroll
            for (int ch = 0; ch < 4; ch++) {
                uint32_t regs[32];
                TC_LD_X32(regs, tmem + ch * 32);
                TC_WAIT_LD();
                const int cb = ch * 32;
#pragma unroll
                for (int q = 0; q < 32; q++) {
                    float dv = __uint_as_float(regs[q]);
                    s += fmaxf(dv + b2s[cb + q], 0.f) * w3s[cb + q];
                }
            }
            MBAR_WAIT(sbase + P_MB + 8, ii & 1);
            TC_FENCE_AFTER();
#pragma unroll
            for (int ch = 0; ch < 4; ch++) {
                uint32_t regs[32];
                TC_LD_X32(regs, tmem + 128 + ch * 32);
                TC_WAIT_LD();
                const int cb = 128 + ch * 32;
#pragma unroll
                for (int q = 0; q < 32; q++) {
                    float dv = __uint_as_float(regs[q]);
                    s += fmaxf(dv + b2s[cb + q], 0.f) * w3s[cb + q];
                }
            }
            TC_FENCE_BEFORE();
            red[w * 32 + lane] = s;
        } else {
            // producer warps: wait for MMA's last h1 read, then fill h1(ii+1)
            MBAR_WAIT(sbase + P_MB + 8, ii & 1);
            if (ii < 3) {
                const __nv_bfloat16* ai = ashh + (ii + 1) * 256;
                const int tid2 = tid - 128;
                for (int c = tid2; c < 128 * 32; c += 128) {
                    int j = c >> 5, g = c & 31;
                    uint4 bv = *reinterpret_cast<const uint4*>(g_Bfh + (j0 + j) * NH + g * 8);
                    const __nv_bfloat162* ap = reinterpret_cast<const __nv_bfloat162*>(ai + g * 8);
                    __nv_bfloat162* hv = reinterpret_cast<__nv_bfloat162*>(&bv);
#pragma unroll
                    for (int q = 0; q < 4; q++) hv[q] = __hmax2(__hadd2(hv[q], ap[q]), zero2);
                    uint32_t off = (uint32_t)((j >> 3) * 1024 + (g >> 3) * 16384
                                            + (j & 7) * 128 + (g & 7) * 16);
                    *reinterpret_cast<uint4*>(h1s + sw128(off)) = bv;
                }
            }
        }
        __syncthreads();

        if (tid < 128) {
            int j = j0 + tid;
            if (j > i) {
                float logit = red[tid] + b3v[0];
                float lab = (j < NM) ? 1.f : 0.f;
                bacc += fmaxf(logit, 0.f) - logit * lab + log1pf(expf(-fabsf(logit)));
            }
        }
    }
    __syncthreads();
    if (w == 0) TC_DEALLOC(tmem, NH);

#else
    // ============== wmma fallback path (compute_103 PTX) ==============
    constexpr int LDH = 264;
    __nv_bfloat16* h1a = reinterpret_cast<__nv_bfloat16*>(dyn);
    __nv_bfloat16* h1b = reinterpret_cast<__nv_bfloat16*>(dyn + 67584);
    float* cscr = reinterpret_cast<float*>(dyn + 135168);
    float* part = reinterpret_cast<float*>(dyn + 151552);
    const int plocal = lane & 15, half = lane >> 4;
    const int c0 = w * 32;

    wmma::fragment<wmma::matrix_b, 16, 16, 16, __nv_bfloat16, wmma::col_major> bf0[16], bf1[16];
#pragma unroll
    for (int k = 0; k < 16; k++) {
        wmma::load_matrix_sync(bf0[k], g_W2h + c0 * NH + k * 16, NH);
        wmma::load_matrix_sync(bf1[k], g_W2h + (c0 + 16) * NH + k * 16, NH);
    }
    float* cs = cscr + w * 512;

    for (int ip = 0; ip < 2; ip++) {
        const int i0 = ibase + 2 * ip, i1 = i0 + 1;
        __syncthreads();
        const __nv_bfloat16* a0 = ashh + 2 * ip * 256;
        const __nv_bfloat16* a1 = a0 + 256;
        for (int c = tid; c < 128 * 32; c += 256) {
            int j = c >> 5, g = c & 31;
            uint4 bv = *reinterpret_cast<const uint4*>(g_Bfh + (j0 + j) * NH + g * 8);
            const __nv_bfloat162* ap0 = reinterpret_cast<const __nv_bfloat162*>(a0 + g * 8);
            const __nv_bfloat162* ap1 = reinterpret_cast<const __nv_bfloat162*>(a1 + g * 8);
            uint4 va = bv, vb = bv;
            __nv_bfloat162* ha = reinterpret_cast<__nv_bfloat162*>(&va);
            __nv_bfloat162* hb = reinterpret_cast<__nv_bfloat162*>(&vb);
#pragma unroll
            for (int q = 0; q < 4; q++) {
                ha[q] = __hmax2(__hadd2(ha[q], ap0[q]), zero2);
                hb[q] = __hmax2(__hadd2(hb[q], ap1[q]), zero2);
            }
            *reinterpret_cast<uint4*>(h1a + j * LDH + g * 8) = va;
            *reinterpret_cast<uint4*>(h1b + j * LDH + g * 8) = vb;
        }
        __syncthreads();

        for (int mt = 0; mt < 8; mt++) {
            wmma::fragment<wmma::accumulator, 16, 16, 16, float> acc00, acc01, acc10, acc11;
            wmma::fill_fragment(acc00, 0.f); wmma::fill_fragment(acc01, 0.f);
            wmma::fill_fragment(acc10, 0.f); wmma::fill_fragment(acc11, 0.f);
#pragma unroll
            for (int k = 0; k < 16; k++) {
                wmma::fragment<wmma::matrix_a, 16, 16, 16, __nv_bfloat16, wmma::row_major> afa, afb;
                wmma::load_matrix_sync(afa, h1a + mt * 16 * LDH + k * 16, LDH);
                wmma::load_matrix_sync(afb, h1b + mt * 16 * LDH + k * 16, LDH);
                wmma::mma_sync(acc00, afa, bf0[k], acc00);
                wmma::mma_sync(acc01, afa, bf1[k], acc01);
                wmma::mma_sync(acc10, afb, bf0[k], acc10);
                wmma::mma_sync(acc11, afb, bf1[k], acc11);
            }
            wmma::store_matrix_sync(cs, acc00, 16, wmma::mem_row_major);
            wmma::store_matrix_sync(cs + 256, acc01, 16, wmma::mem_row_major);
            __syncwarp();
            {
                const float* cp = cs + half * 256 + plocal * 16;
                const int cb = c0 + half * 16;
                float s = 0.f;
#pragma unroll
                for (int q = 0; q < 16; q++)
                    s += fmaxf(cp[q] + b2s[cb + q], 0.f) * w3s[cb + q];
                s += __shfl_down_sync(0xffffffffu, s, 16);
                if (half == 0) part[(mt * 16 + plocal) * 8 + w] = s;
            }
            __syncwarp();
            wmma::store_matrix_sync(cs, acc10, 16, wmma::mem_row_major);
            wmma::store_matrix_sync(cs + 256, acc11, 16, wmma::mem_row_major);
            __syncwarp();
            {
                const float* cp = cs + half * 256 + plocal * 16;
                const int cb = c0 + half * 16;
                float s = 0.f;
#pragma unroll
                for (int q = 0; q < 16; q++)
                    s += fmaxf(cp[q] + b2s[cb + q], 0.f) * w3s[cb + q];
                s += __shfl_down_sync(0xffffffffu, s, 16);
                if (half == 0) part[1024 + (mt * 16 + plocal) * 8 + w] = s;
            }
            __syncwarp();
        }
        __syncthreads();

        if (tid < 128) {
            int j = j0 + tid;
            float l0 = b3v[0], l1 = l0;
#pragma unroll
            for (int q = 0; q < 8; q++) { l0 += part[tid * 8 + q]; l1 += part[1024 + tid * 8 + q]; }
            if (j > i0) {
                float lab = (j < NM) ? 1.f : 0.f;
                bacc += fmaxf(l0, 0.f) - l0 * lab + log1pf(expf(-fabsf(l0)));
            }
            if (j > i1) {
                float lab = (j < NM) ? 1.f : 0.f;
                bacc += fmaxf(l1, 0.f) - l1 * lab + log1pf(expf(-fabsf(l1)));
            }
        }
    }
#endif
    __syncthreads();

    // block reduce bacc
    rr[tid] = bacc;
    __syncthreads();
    for (int st = 128; st > 0; st >>= 1) {
        if (tid < st) rr[tid] += rr[tid + st];
        __syncthreads();
    }
    __shared__ bool isLast;
    if (tid == 0) {
        g_bcep[blockIdx.y * 32 + blockIdx.x] = rr[0];
        __threadfence();
        unsigned v = atomicAdd(&g_ctr, 1u);
        isLast = (v == 127u);
    }
    __syncthreads();
    if (!isLast) return;

    // ----- final reduce (last block, deterministic order) -----
    float b = (tid < 128) ? g_bcep[tid] : 0.f;
    rr[tid] = b;
    __syncthreads();
    for (int st = 128; st > 0; st >>= 1) {
        if (tid < st) rr[tid] += rr[tid + st];
        __syncthreads();
    }
    float bsum = rr[0];
    __syncthreads();

    float c = 0.f;
    if (tid < NQ) {
        int i = tid;
        float den = 0.f, pr = 0.f;
#pragma unroll
        for (int q = 0; q < 8; q++) {
            den += g_denomp[i * 8 + q];
            pr += g_pairp[i * 8 + q];
        }
        c = (float)(NQ - 1 - i) * logf(den) - TAU_INV * pr;
    }
    rr[tid] = c;
    __syncthreads();
    for (int st = 128; st > 0; st >>= 1) {
        if (tid < st) rr[tid] += rr[tid + st];
        __syncthreads();
    }
    if (tid == 0) {
        float closs = (-2.0f * (float)(NQ - 1) / (float)NQ) * rr[0];
        out[0] = closs + bsum / PCOUNT;
    }
}

// ---------------- launch ----------------
extern "C" void kernel_launch(void* const* d_in, const int* in_sizes, int n_in,
                              void* d_out, int out_size) {
    const float* emb = (const float*)d_in[0];
    const float* W1  = (const float*)d_in[1];
    const float* b1  = (const float*)d_in[2];
    const float* W2  = (const float*)d_in[3];
    const float* b2  = (const float*)d_in[4];
    const float* W3  = (const float*)d_in[5];
    const float* b3  = (const float*)d_in[6];

    cudaFuncSetAttribute(k_mid, cudaFuncAttributeMaxDynamicSharedMemorySize, B_SMEM);
    cudaFuncSetAttribute(k_pair, cudaFuncAttributeMaxDynamicSharedMemorySize, P_SMEM);

    k_prep<<<128 + 112, 256>>>(emb, W1, W2);
    k_mid<<<80 + 64, 256, B_SMEM>>>();
    k_pair<<<dim3(32, 4), 256, P_SMEM>>>(b1, b2, W3, b3, (float*)d_out);
}

// round 15
// speedup vs baseline: 1.1032x; 1.1032x over previous
#include <cuda_runtime.h>
#include <cuda_bf16.h>
#include <mma.h>
#include <cstdint>

using namespace nvcuda;

constexpr int NB = 512;   // batch B
constexpr int ND = 768;   // D
constexpr int NH = 256;   // H
constexpr int NQ = 128;   // n = B/4
constexpr int NM = 256;   // m = B/2
constexpr float TAU_INV = 2.0f;
constexpr float PCOUNT = 57280.0f;

// ---------------- scratch ----------------
__device__ __nv_bfloat16 g_zh[NB * ND];
__device__ __nv_bfloat16 g_W1h[NH * 2 * ND];
__device__ __nv_bfloat16 g_W2h[NH * NH];
__device__ float g_A[NQ * NH];
__device__ __nv_bfloat16 g_Bfh[NB * NH];
__device__ float g_denomp[NQ * 8];
__device__ float g_pairp[NQ * 8];
__device__ float g_bcep[128];
__device__ unsigned g_ctr;    // k_pair last-block counter
__device__ unsigned g_s1;     // k_mid grid sync

// release/acquire grid barrier over `count` co-resident blocks
__device__ __forceinline__ void grid_sync(unsigned* ctr, unsigned count) {
    __syncthreads();
    __threadfence();
    if (threadIdx.x == 0) {
        atomicAdd(ctr, 1u);
        while (*(volatile unsigned*)ctr < count) __nanosleep(64);
    }
    __syncthreads();
    __threadfence();
}

// ================= kernel A+B fused: prep phase + featw/contrast ===========
constexpr int LZA = 776;
constexpr int LZB = 776;
constexpr int LSS = 68;
constexpr int B_ZB = 16 * LZA * 2;                 // 24832
constexpr int B_S0 = B_ZB + 64 * LZB * 2;          // 124160
constexpr int B_S1 = B_S0 + 16 * LSS * 4;          // 128512
constexpr int B_SMEM = B_S1 + 16 * LSS * 4;        // 132864

__global__ void __launch_bounds__(256, 1)
k_mid(const float* __restrict__ x,
      const float* __restrict__ W1, const float* __restrict__ W2) {
    extern __shared__ __align__(16) char dyn[];
    __nv_bfloat16* za = reinterpret_cast<__nv_bfloat16*>(dyn);
    const int tid = threadIdx.x;
    const int w = tid >> 5, lane = tid & 31;
    const int bid = blockIdx.x;   // 0..143

    // ---------------- phase 0: norm (bid<128) + weight convert (all) -------
    if (bid == 0 && tid == 0) g_ctr = 0;
    if (bid < 128) {
        __shared__ float sm[8];
        const int r = bid * 4 + (w >> 1);
        const int hoff = (w & 1) * 384;
        const float* xr = x + r * ND;
        float s = 0.f;
#pragma unroll
        for (int q = 0; q < 12; q++) { float v = xr[hoff + lane + q * 32]; s += v * v; }
#pragma unroll
        for (int o = 16; o; o >>= 1) s += __shfl_down_sync(0xffffffffu, s, o);
        if (lane == 0) sm[w] = s;
        __syncthreads();
        float inv = 1.0f / fmaxf(sqrtf(sm[w & ~1] + sm[(w & ~1) + 1]), 1e-12f);
        const int poff = (w & 1) * 192;
#pragma unroll
        for (int q = 0; q < 6; q++) {
            int p = poff + lane + q * 32;
            __nv_bfloat162 v = __floats2bfloat162_rn(xr[2 * p] * inv, xr[2 * p + 1] * inv);
            *reinterpret_cast<__nv_bfloat162*>(g_zh + r * ND + 2 * p) = v;
        }
    }
    {
        // 144 blocks x 800 float4 covers W1 (393216) + W2 (65536) = 458752 floats
        const int N1 = NH * 2 * ND;
        const int TOT = N1 + NH * NH;
        for (int c = tid; c < 800; c += 256) {
            int off = (bid * 800 + c) * 4;
            if (off < TOT) {
                const float* src;
                __nv_bfloat16* dst;
                int o;
                if (off < N1) { src = W1; dst = g_W1h; o = off; }
                else          { src = W2; dst = g_W2h; o = off - N1; }
                float4 v = *reinterpret_cast<const float4*>(src + o);
                *reinterpret_cast<__nv_bfloat162*>(dst + o)     = __floats2bfloat162_rn(v.x, v.y);
                *reinterpret_cast<__nv_bfloat162*>(dst + o + 2) = __floats2bfloat162_rn(v.z, v.w);
            }
        }
    }
    grid_sync(&g_s1, 144u);

    // ---------------- phase 1: featw (bid<80) | contrast (bid>=80) ---------
    if (bid < 80) {
        const int t = bid;
        const bool isA = t < 16;
        const int rbase = (isA ? (t >> 1) : ((t - 16) >> 1)) * 16;
        const int colh = t & 1;
        const int off = isA ? 0 : ND;

        for (int c = tid; c < 16 * (ND / 8); c += 256) {
            int r = c / (ND / 8), d8 = c % (ND / 8);
            *reinterpret_cast<uint4*>(za + r * LZA + d8 * 8) =
                *reinterpret_cast<const uint4*>(g_zh + (rbase + r) * ND + d8 * 8);
        }
        __syncthreads();

        const int h = colh * 128 + w * 16;
        wmma::fragment<wmma::accumulator, 16, 16, 16, float> ce, co;
        wmma::fill_fragment(ce, 0.f);
        wmma::fill_fragment(co, 0.f);
#pragma unroll 4
        for (int kc = 0; kc < ND / 16; kc += 2) {
            wmma::fragment<wmma::matrix_a, 16, 16, 16, __nv_bfloat16, wmma::row_major> ae, ao;
            wmma::fragment<wmma::matrix_b, 16, 16, 16, __nv_bfloat16, wmma::col_major> be, bo;
            wmma::load_matrix_sync(ae, za + kc * 16, LZA);
            wmma::load_matrix_sync(ao, za + (kc + 1) * 16, LZA);
            wmma::load_matrix_sync(be, g_W1h + h * (2 * ND) + off + kc * 16, 2 * ND);
            wmma::load_matrix_sync(bo, g_W1h + h * (2 * ND) + off + (kc + 1) * 16, 2 * ND);
            wmma::mma_sync(ce, ae, be, ce);
            wmma::mma_sync(co, ao, bo, co);
        }
#pragma unroll
        for (int e = 0; e < ce.num_elements; e++) ce.x[e] += co.x[e];

        if (isA) {
            wmma::store_matrix_sync(g_A + rbase * NH + h, ce, NH, wmma::mem_row_major);
        } else {
            float* cbuf = reinterpret_cast<float*>(dyn);
            __syncthreads();
            wmma::store_matrix_sync(cbuf + w * 16, ce, 132, wmma::mem_row_major);
            __syncthreads();
            for (int c = tid; c < 16 * 64; c += 256) {
                int r = c >> 6, p = c & 63;
                __nv_bfloat162 v = __floats2bfloat162_rn(cbuf[r * 132 + 2 * p],
                                                         cbuf[r * 132 + 2 * p + 1]);
                *reinterpret_cast<__nv_bfloat162*>(g_Bfh + (rbase + r) * NH + colh * 128 + 2 * p) = v;
            }
        }
    } else {
        const int vb = bid - 80;
        const int bx = vb >> 3;
        const int by = vb & 7;
        const int ibase = bx * 16;
        const int kbase = by * 64;

        __nv_bfloat16* zb = reinterpret_cast<__nv_bfloat16*>(dyn + B_ZB);
        float* S0 = reinterpret_cast<float*>(dyn + B_S0);
        float* S1 = reinterpret_cast<float*>(dyn + B_S1);

        for (int c = tid; c < 16 * (ND / 8); c += 256) {
            int r = c / (ND / 8), d8 = c % (ND / 8);
            *reinterpret_cast<uint4*>(za + r * LZA + d8 * 8) =
                *reinterpret_cast<const uint4*>(g_zh + (ibase + r) * ND + d8 * 8);
        }
        for (int c = tid; c < 64 * (ND / 8); c += 256) {
            int r = c / (ND / 8), d8 = c % (ND / 8);
            *reinterpret_cast<uint4*>(zb + r * LZB + d8 * 8) =
                *reinterpret_cast<const uint4*>(g_zh + (kbase + r) * ND + d8 * 8);
        }
        __syncthreads();

        const int wn = w & 3;
        const int wd = w >> 2;
        const int kcol = wn * 16;
        const int d0 = wd * 384;

        wmma::fragment<wmma::accumulator, 16, 16, 16, float> cf0, cf1;
        wmma::fill_fragment(cf0, 0.f);
        wmma::fill_fragment(cf1, 0.f);
#pragma unroll 4
        for (int kc = 0; kc < 24; kc += 2) {
            wmma::fragment<wmma::matrix_a, 16, 16, 16, __nv_bfloat16, wmma::row_major> a0, a1;
            wmma::fragment<wmma::matrix_b, 16, 16, 16, __nv_bfloat16, wmma::col_major> b0, b1;
            wmma::load_matrix_sync(a0, za + d0 + kc * 16, LZA);
            wmma::load_matrix_sync(b0, zb + kcol * LZB + d0 + kc * 16, LZB);
            wmma::load_matrix_sync(a1, za + d0 + (kc + 1) * 16, LZA);
            wmma::load_matrix_sync(b1, zb + kcol * LZB + d0 + (kc + 1) * 16, LZB);
            wmma::mma_sync(cf0, a0, b0, cf0);
            wmma::mma_sync(cf1, a1, b1, cf1);
        }
#pragma unroll
        for (int e = 0; e < cf0.num_elements; e++) cf0.x[e] += cf1.x[e];
        wmma::store_matrix_sync((wd ? S1 : S0) + kcol, cf0, LSS, wmma::mem_row_major);
        __syncthreads();

#pragma unroll
        for (int rr = 2 * w; rr <= 2 * w + 1; rr++) {
            int i = ibase + rr;
            float dacc = 0.f, pacc = 0.f;
#pragma unroll
            for (int cc = 0; cc < 2; cc++) {
                int c = lane + cc * 32;
                int k = kbase + c;
                float s = S0[rr * LSS + c] + S1[rr * LSS + c];
                if (k != i) dacc += expf(TAU_INV * s);
                if (k > i && k < NQ) pacc += s;
            }
#pragma unroll
            for (int o = 16; o; o >>= 1) {
                dacc += __shfl_down_sync(0xffffffffu, dacc, o);
                pacc += __shfl_down_sync(0xffffffffu, pacc, o);
            }
            if (lane == 0) {
                g_denomp[i * 8 + by] = dacc;
                g_pairp[i * 8 + by] = pacc;
            }
        }
    }
}

// ================= kernel C: pair MLP (tcgen05, split-N pipelined) =========
constexpr int U_SZ  = 196608;
constexpr int P_ASH = U_SZ;                 // 2048
constexpr int P_B2S = P_ASH + 2048;         // 1024
constexpr int P_W3S = P_B2S + 1024;         // 1024
constexpr int P_RR  = P_W3S + 1024;         // 1024
constexpr int P_RED = P_RR + 1024;          // 2048 (4 x 128 partials)
constexpr int P_TM  = P_RED + 2048;         // 16
constexpr int P_MB  = P_TM + 16;            // 32 (two mbarriers)
constexpr int P_SMEM = P_MB + 32;           // 205856

#if defined(__CUDA_ARCH_FEAT_SM103_ALL)
__device__ __forceinline__ uint32_t smem_u32(const void* p) {
    uint32_t a;
    asm("{ .reg .u64 t; cvta.to.shared.u64 t, %1; cvt.u32.u64 %0, t; }" : "=r"(a) : "l"(p));
    return a;
}
__device__ __forceinline__ uint32_t elect_one() {
    uint32_t p;
    asm volatile("{\n\t.reg .pred p;\n\telect.sync _|p, 0xFFFFFFFF;\n\tselp.b32 %0, 1, 0, p;\n\t}" : "=r"(p));
    return p;
}
#define MBAR_INIT(a, n) asm volatile("mbarrier.init.shared.b64 [%0], %1;" :: "r"(a), "r"(n) : "memory")
#define MBAR_WAIT(a, ph) do { \
    uint32_t _m = (a), _p = (ph), _d; \
    asm volatile("{\n\t.reg .pred p;\n\tmbarrier.try_wait.parity.acquire.cta.shared::cta.b64 p, [%1], %2;\n\tselp.b32 %0, 1, 0, p;\n\t}" \
        : "=r"(_d) : "r"(_m), "r"(_p) : "memory"); \
    if (!_d) { \
        asm volatile("{\n\t.reg .pred P1;\n\tWL_%=:\n\tmbarrier.try_wait.parity.acquire.cta.shared::cta.b64 P1, [%0], %1, 0x989680;\n\t@P1 bra.uni WD_%=;\n\tbra.uni WL_%=;\n\tWD_%=:\n\t}" \
            :: "r"(_m), "r"(_p) : "memory"); \
    } } while (0)
#define TC_ALLOC(sa, n)  asm volatile("tcgen05.alloc.cta_group::1.sync.aligned.shared::cta.b32 [%0], %1;" :: "r"(sa), "r"(n) : "memory")
#define TC_RELINQ()      asm volatile("tcgen05.relinquish_alloc_permit.cta_group::1.sync.aligned;")
#define TC_DEALLOC(t, n) asm volatile("tcgen05.dealloc.cta_group::1.sync.aligned.b32 %0, %1;" :: "r"(t), "r"(n))
#define TC_COMMIT(mb)    asm volatile("tcgen05.commit.cta_group::1.mbarrier::arrive::one.shared::cluster.b64 [%0];" :: "r"(mb) : "memory")
#define TC_WAIT_LD()     asm volatile("tcgen05.wait::ld.sync.aligned;" ::: "memory")
#define TC_FENCE_AFTER() asm volatile("tcgen05.fence::after_thread_sync;" ::: "memory")
#define TC_FENCE_BEFORE() asm volatile("tcgen05.fence::before_thread_sync;" ::: "memory")
#define FENCE_ASYNC()    asm volatile("fence.proxy.async.shared::cta;" ::: "memory")
#define TC_LD_X32(r, ta) \
    asm volatile("tcgen05.ld.sync.aligned.32x32b.x32.b32 " \
        "{%0, %1, %2, %3, %4, %5, %6, %7, %8, %9, %10, %11, %12, %13, %14, %15, " \
        " %16, %17, %18, %19, %20, %21, %22, %23, %24, %25, %26, %27, %28, %29, %30, %31}, [%32];" \
        : "=r"((r)[0]), "=r"((r)[1]), "=r"((r)[2]), "=r"((r)[3]), \
          "=r"((r)[4]), "=r"((r)[5]), "=r"((r)[6]), "=r"((r)[7]), \
          "=r"((r)[8]), "=r"((r)[9]), "=r"((r)[10]), "=r"((r)[11]), \
          "=r"((r)[12]), "=r"((r)[13]), "=r"((r)[14]), "=r"((r)[15]), \
          "=r"((r)[16]), "=r"((r)[17]), "=r"((r)[18]), "=r"((r)[19]), \
          "=r"((r)[20]), "=r"((r)[21]), "=r"((r)[22]), "=r"((r)[23]), \
          "=r"((r)[24]), "=r"((r)[25]), "=r"((r)[26]), "=r"((r)[27]), \
          "=r"((r)[28]), "=r"((r)[29]), "=r"((r)[30]), "=r"((r)[31]) \
        : "r"(ta))
__device__ __forceinline__ void mma_f16_ss_cg1(uint32_t d, uint64_t a, uint64_t b,
                                               uint32_t idesc, bool acc) {
    uint32_t en = acc ? 1u : 0u, zero = 0u;
    asm volatile(
        "{\n\t.reg .pred p;\n\tsetp.ne.u32 p, %5, 0;\n\t"
        "tcgen05.mma.cta_group::1.kind::f16 [%0], %1, %2, %3, {%4, %4, %4, %4}, p;\n\t}"
        :: "r"(d), "l"(a), "l"(b), "r"(idesc), "r"(zero), "r"(en) : "memory");
}
__device__ __forceinline__ uint64_t make_desc(uint32_t addr) {
    const uint64_t base = (uint64_t(2) << 61) | (uint64_t(1) << 46)
                        | (uint64_t(64) << 32) | (uint64_t(1) << 16);
    return base | ((uint64_t)(addr >> 4) & 0x3FFF);
}
__device__ __forceinline__ uint32_t sw128(uint32_t x) { return x ^ ((x >> 3) & 0x70); }
// N=128 half-GEMM idesc: f32 accum, bf16 x bf16, N=128, M=128
constexpr uint32_t IDESC_HALF = (1u << 4) | (1u << 7) | (1u << 10)
                              | (16u << 17) | (8u << 24);
#endif

__global__ void __launch_bounds__(256, 1)
k_pair(const float* __restrict__ b1, const float* __restrict__ b2,
       const float* __restrict__ w3, const float* __restrict__ b3v,
       float* __restrict__ out) {
    extern __shared__ __align__(16) char dyn[];
    __nv_bfloat16* ashh = reinterpret_cast<__nv_bfloat16*>(dyn + P_ASH);
    float* b2s = reinterpret_cast<float*>(dyn + P_B2S);
    float* w3s = reinterpret_cast<float*>(dyn + P_W3S);
    float* rr  = reinterpret_cast<float*>(dyn + P_RR);

    const int ibase = blockIdx.x * 4;
    const int j0 = blockIdx.y * 128;
    const int tid = threadIdx.x;
    const int w = tid >> 5, lane = tid & 31;
    const __nv_bfloat162 zero2 = __floats2bfloat162_rn(0.f, 0.f);
    float bacc = 0.f;

    {
        int h = tid;
        float bb = b1[h];
#pragma unroll
        for (int ii = 0; ii < 4; ii++)
            ashh[ii * 256 + h] = __float2bfloat16(g_A[(ibase + ii) * NH + h] + bb);
        b2s[h] = b2[h];
        w3s[h] = w3[h];
    }

#if defined(__CUDA_ARCH_FEAT_SM103_ALL)
    // ============== tcgen05 path: split-N pipelined ==============
    char* w2s = dyn;                 // swizzled W2, 131072 B
    char* h1s = dyn + 131072;        // swizzled h1, 65536 B
    float* red = reinterpret_cast<float*>(dyn + P_RED);   // [4][128]
    const uint32_t sbase = smem_u32(dyn);

    if (w == 0) { TC_ALLOC(sbase + P_TM, NH); TC_RELINQ(); }
    if (tid == 0) {
        MBAR_INIT(sbase + P_MB, 1);
        MBAR_INIT(sbase + P_MB + 8, 1);
    }

    for (int c = tid; c < 256 * 32; c += 256) {
        int n = c >> 5, g = c & 31;
        uint32_t off = (uint32_t)((n >> 3) * 1024 + (g >> 3) * 32768
                                + (n & 7) * 128 + (g & 7) * 16);
        *reinterpret_cast<uint4*>(w2s + sw128(off)) =
            *reinterpret_cast<const uint4*>(g_W2h + n * NH + g * 8);
    }
    __syncthreads();

    uint32_t tmem;
    asm volatile("ld.shared.b32 %0, [%1];" : "=r"(tmem) : "r"(sbase + P_TM));

    const uint64_t a_base = make_desc(sbase + 131072);
    const uint64_t b_base = make_desc(sbase);
    const int row = (w & 3) * 32 + lane;   // this lane's pair row (subpartition)
    const int chalf = (w >> 2) * 64;       // this warp's 64-col slice of a half

    for (int ii = 0; ii < 4; ii++) {
        const int i = ibase + ii;
        const __nv_bfloat16* ai = ashh + ii * 256;
        for (int c = tid; c < 128 * 32; c += 256) {
            int j = c >> 5, g = c & 31;
            uint4 bv = *reinterpret_cast<const uint4*>(g_Bfh + (j0 + j) * NH + g * 8);
            const __nv_bfloat162* ap = reinterpret_cast<const __nv_bfloat162*>(ai + g * 8);
            __nv_bfloat162* hv = reinterpret_cast<__nv_bfloat162*>(&bv);
#pragma unroll
            for (int q = 0; q < 4; q++) hv[q] = __hmax2(__hadd2(hv[q], ap[q]), zero2);
            uint32_t off = (uint32_t)((j >> 3) * 1024 + (g >> 3) * 16384
                                    + (j & 7) * 128 + (g & 7) * 16);
            *reinterpret_cast<uint4*>(h1s + sw128(off)) = bv;
        }
        FENCE_ASYNC();
        __syncthreads();

        if (w == 0) {
            if (elect_one()) {
                // half 0: W2 rows 0-127 -> D cols 0-127
#pragma unroll
                for (int ks = 0; ks < 16; ks++) {
                    uint64_t ad = a_base + (uint64_t)((ks >> 2) * 1024 + (ks & 3) * 2);
                    uint64_t bd = b_base + (uint64_t)((ks >> 2) * 2048 + (ks & 3) * 2);
                    mma_f16_ss_cg1(tmem, ad, bd, IDESC_HALF, ks > 0);
                }
                TC_COMMIT(sbase + P_MB);
                // half 1: W2 rows 128-255 -> D cols 128-255
#pragma unroll
                for (int ks = 0; ks < 16; ks++) {
                    uint64_t ad = a_base + (uint64_t)((ks >> 2) * 1024 + (ks & 3) * 2);
                    uint64_t bd = b_base + 1024 + (uint64_t)((ks >> 2) * 2048 + (ks & 3) * 2);
                    mma_f16_ss_cg1(tmem + 128, ad, bd, IDESC_HALF, ks > 0);
                }
                TC_COMMIT(sbase + P_MB + 8);
            }
        }

        // epilogue half 0 overlaps tensor pipe running half 1
        MBAR_WAIT(sbase + P_MB, ii & 1);
        TC_FENCE_AFTER();
        {
            float s = 0.f;
#pragma unroll
            for (int ch = 0; ch < 2; ch++) {
                uint32_t regs[32];
                TC_LD_X32(regs, tmem + chalf + ch * 32);
                TC_WAIT_LD();
                const int cb = chalf + ch * 32;
#pragma unroll
                for (int q = 0; q < 32; q++) {
                    float dv = __uint_as_float(regs[q]);
                    s += fmaxf(dv + b2s[cb + q], 0.f) * w3s[cb + q];
                }
            }
            red[(w >> 2) * 128 + row] = s;
        }
        // epilogue half 1
        MBAR_WAIT(sbase + P_MB + 8, ii & 1);
        TC_FENCE_AFTER();
        {
            float s = 0.f;
#pragma unroll
            for (int ch = 0; ch < 2; ch++) {
                uint32_t regs[32];
                TC_LD_X32(regs, tmem + 128 + chalf + ch * 32);
                TC_WAIT_LD();
                const int cb = 128 + chalf + ch * 32;
#pragma unroll
                for (int q = 0; q < 32; q++) {
                    float dv = __uint_as_float(regs[q]);
                    s += fmaxf(dv + b2s[cb + q], 0.f) * w3s[cb + q];
                }
            }
            TC_FENCE_BEFORE();
            red[256 + (w >> 2) * 128 + row] = s;
        }
        __syncthreads();

        if (tid < 128) {
            int j = j0 + tid;
            if (j > i) {
                float logit = red[tid] + red[128 + tid] + red[256 + tid]
                            + red[384 + tid] + b3v[0];
                float lab = (j < NM) ? 1.f : 0.f;
                bacc += fmaxf(logit, 0.f) - logit * lab + log1pf(expf(-fabsf(logit)));
            }
        }
        __syncthreads();
    }
    if (w == 0) TC_DEALLOC(tmem, NH);

#else
    // ============== wmma fallback path (compute_103 PTX) ==============
    constexpr int LDH = 264;
    __nv_bfloat16* h1a = reinterpret_cast<__nv_bfloat16*>(dyn);
    __nv_bfloat16* h1b = reinterpret_cast<__nv_bfloat16*>(dyn + 67584);
    float* cscr = reinterpret_cast<float*>(dyn + 135168);
    float* part = reinterpret_cast<float*>(dyn + 151552);
    const int plocal = lane & 15, half = lane >> 4;
    const int c0 = w * 32;

    wmma::fragment<wmma::matrix_b, 16, 16, 16, __nv_bfloat16, wmma::col_major> bf0[16], bf1[16];
#pragma unroll
    for (int k = 0; k < 16; k++) {
        wmma::load_matrix_sync(bf0[k], g_W2h + c0 * NH + k * 16, NH);
        wmma::load_matrix_sync(bf1[k], g_W2h + (c0 + 16) * NH + k * 16, NH);
    }
    float* cs = cscr + w * 512;

    for (int ip = 0; ip < 2; ip++) {
        const int i0 = ibase + 2 * ip, i1 = i0 + 1;
        __syncthreads();
        const __nv_bfloat16* a0 = ashh + 2 * ip * 256;
        const __nv_bfloat16* a1 = a0 + 256;
        for (int c = tid; c < 128 * 32; c += 256) {
            int j = c >> 5, g = c & 31;
            uint4 bv = *reinterpret_cast<const uint4*>(g_Bfh + (j0 + j) * NH + g * 8);
            const __nv_bfloat162* ap0 = reinterpret_cast<const __nv_bfloat162*>(a0 + g * 8);
            const __nv_bfloat162* ap1 = reinterpret_cast<const __nv_bfloat162*>(a1 + g * 8);
            uint4 va = bv, vb = bv;
            __nv_bfloat162* ha = reinterpret_cast<__nv_bfloat162*>(&va);
            __nv_bfloat162* hb = reinterpret_cast<__nv_bfloat162*>(&vb);
#pragma unroll
            for (int q = 0; q < 4; q++) {
                ha[q] = __hmax2(__hadd2(ha[q], ap0[q]), zero2);
                hb[q] = __hmax2(__hadd2(hb[q], ap1[q]), zero2);
            }
            *reinterpret_cast<uint4*>(h1a + j * LDH + g * 8) = va;
            *reinterpret_cast<uint4*>(h1b + j * LDH + g * 8) = vb;
        }
        __syncthreads();

        for (int mt = 0; mt < 8; mt++) {
            wmma::fragment<wmma::accumulator, 16, 16, 16, float> acc00, acc01, acc10, acc11;
            wmma::fill_fragment(acc00, 0.f); wmma::fill_fragment(acc01, 0.f);
            wmma::fill_fragment(acc10, 0.f); wmma::fill_fragment(acc11, 0.f);
#pragma unroll
            for (int k = 0; k < 16; k++) {
                wmma::fragment<wmma::matrix_a, 16, 16, 16, __nv_bfloat16, wmma::row_major> afa, afb;
                wmma::load_matrix_sync(afa, h1a + mt * 16 * LDH + k * 16, LDH);
                wmma::load_matrix_sync(afb, h1b + mt * 16 * LDH + k * 16, LDH);
                wmma::mma_sync(acc00, afa, bf0[k], acc00);
                wmma::mma_sync(acc01, afa, bf1[k], acc01);
                wmma::mma_sync(acc10, afb, bf0[k], acc10);
                wmma::mma_sync(acc11, afb, bf1[k], acc11);
            }
            wmma::store_matrix_sync(cs, acc00, 16, wmma::mem_row_major);
            wmma::store_matrix_sync(cs + 256, acc01, 16, wmma::mem_row_major);
            __syncwarp();
            {
                const float* cp = cs + half * 256 + plocal * 16;
                const int cb = c0 + half * 16;
                float s = 0.f;
#pragma unroll
                for (int q = 0; q < 16; q++)
                    s += fmaxf(cp[q] + b2s[cb + q], 0.f) * w3s[cb + q];
                s += __shfl_down_sync(0xffffffffu, s, 16);
                if (half == 0) part[(mt * 16 + plocal) * 8 + w] = s;
            }
            __syncwarp();
            wmma::store_matrix_sync(cs, acc10, 16, wmma::mem_row_major);
            wmma::store_matrix_sync(cs + 256, acc11, 16, wmma::mem_row_major);
            __syncwarp();
            {
                const float* cp = cs + half * 256 + plocal * 16;
                const int cb = c0 + half * 16;
                float s = 0.f;
#pragma unroll
                for (int q = 0; q < 16; q++)
                    s += fmaxf(cp[q] + b2s[cb + q], 0.f) * w3s[cb + q];
                s += __shfl_down_sync(0xffffffffu, s, 16);
                if (half == 0) part[1024 + (mt * 16 + plocal) * 8 + w] = s;
            }
            __syncwarp();
        }
        __syncthreads();

        if (tid < 128) {
            int j = j0 + tid;
            float l0 = b3v[0], l1 = l0;
#pragma unroll
            for (int q = 0; q < 8; q++) { l0 += part[tid * 8 + q]; l1 += part[1024 + tid * 8 + q]; }
            if (j > i0) {
                float lab = (j < NM) ? 1.f : 0.f;
                bacc += fmaxf(l0, 0.f) - l0 * lab + log1pf(expf(-fabsf(l0)));
            }
            if (j > i1) {
                float lab = (j < NM) ? 1.f : 0.f;
                bacc += fmaxf(l1, 0.f) - l1 * lab + log1pf(expf(-fabsf(l1)));
            }
        }
    }
#endif
    __syncthreads();

    // block reduce bacc
    rr[tid] = bacc;
    __syncthreads();
    for (int st = 128; st > 0; st >>= 1) {
        if (tid < st) rr[tid] += rr[tid + st];
        __syncthreads();
    }
    __shared__ bool isLast;
    if (tid == 0) {
        g_bcep[blockIdx.y * 32 + blockIdx.x] = rr[0];
        __threadfence();
        unsigned v = atomicAdd(&g_ctr, 1u);
        isLast = (v == 127u);
    }
    __syncthreads();
    if (!isLast) return;

    // ----- final reduce (last block, deterministic order) -----
    float b = (tid < 128) ? g_bcep[tid] : 0.f;
    rr[tid] = b;
    __syncthreads();
    for (int st = 128; st > 0; st >>= 1) {
        if (tid < st) rr[tid] += rr[tid + st];
        __syncthreads();
    }
    float bsum = rr[0];
    __syncthreads();

    float c = 0.f;
    if (tid < NQ) {
        int i = tid;
        float den = 0.f, pr = 0.f;
#pragma unroll
        for (int q = 0; q < 8; q++) {
            den += g_denomp[i * 8 + q];
            pr += g_pairp[i * 8 + q];
        }
        c = (float)(NQ - 1 - i) * logf(den) - TAU_INV * pr;
    }
    rr[tid] = c;
    __syncthreads();
    for (int st = 128; st > 0; st >>= 1) {
        if (tid < st) rr[tid] += rr[tid + st];
        __syncthreads();
    }
    if (tid == 0) {
        float closs = (-2.0f * (float)(NQ - 1) / (float)NQ) * rr[0];
        out[0] = closs + bsum / PCOUNT;
        g_s1 = 0;   // reset grid-sync counter for next graph replay
    }
}

// ---------------- launch ----------------
extern "C" void kernel_launch(void* const* d_in, const int* in_sizes, int n_in,
                              void* d_out, int out_size) {
    const float* emb = (const float*)d_in[0];
    const float* W1  = (const float*)d_in[1];
    const float* b1  = (const float*)d_in[2];
    const float* W2  = (const float*)d_in[3];
    const float* b2  = (const float*)d_in[4];
    const float* W3  = (const float*)d_in[5];
    const float* b3  = (const float*)d_in[6];

    cudaFuncSetAttribute(k_mid, cudaFuncAttributeMaxDynamicSharedMemorySize, B_SMEM);
    cudaFuncSetAttribute(k_pair, cudaFuncAttributeMaxDynamicSharedMemorySize, P_SMEM);

    k_mid<<<144, 256, B_SMEM>>>(emb, W1, W2);
    k_pair<<<dim3(32, 4), 256, P_SMEM>>>(b1, b2, W3, b3, (float*)d_out);
}

// round 16
// speedup vs baseline: 1.3141x; 1.1912x over previous
#include <cuda_runtime.h>
#include <cuda_bf16.h>
#include <mma.h>
#include <cstdint>

using namespace nvcuda;

constexpr int NB = 512;   // batch B
constexpr int ND = 768;   // D
constexpr int NH = 256;   // H
constexpr int NQ = 128;   // n = B/4
constexpr int NM = 256;   // m = B/2
constexpr float TAU_INV = 2.0f;
constexpr float PCOUNT = 57280.0f;

// ---------------- scratch ----------------
__device__ __nv_bfloat16 g_zh[NB * ND];
__device__ __nv_bfloat16 g_W1h[NH * 2 * ND];
__device__ __nv_bfloat16 g_W2h[NH * NH];
__device__ float g_A[NQ * NH];
__device__ __nv_bfloat16 g_Bfh[NB * NH];
__device__ float g_denomp[NQ * 8];
__device__ float g_pairp[NQ * 8];
__device__ float g_bcep[128];
__device__ unsigned g_ctr;

// ================= kernel A: norm (bx<128) | W1/W2 convert =================
__global__ void k_prep(const float* __restrict__ x,
                       const float* __restrict__ W1, const float* __restrict__ W2) {
    int bx = blockIdx.x;
    if (bx == 0 && threadIdx.x == 0) g_ctr = 0;
    if (bx < 128) {
        __shared__ float sm[8];
        const int w = threadIdx.x >> 5, lane = threadIdx.x & 31;
        const int r = bx * 4 + (w >> 1);
        const int hoff = (w & 1) * 384;
        const float* xr = x + r * ND;
        float s = 0.f;
#pragma unroll
        for (int q = 0; q < 12; q++) { float v = xr[hoff + lane + q * 32]; s += v * v; }
#pragma unroll
        for (int o = 16; o; o >>= 1) s += __shfl_down_sync(0xffffffffu, s, o);
        if (lane == 0) sm[w] = s;
        __syncthreads();
        float inv = 1.0f / fmaxf(sqrtf(sm[w & ~1] + sm[(w & ~1) + 1]), 1e-12f);
        const int poff = (w & 1) * 192;
#pragma unroll
        for (int q = 0; q < 6; q++) {
            int p = poff + lane + q * 32;
            __nv_bfloat162 v = __floats2bfloat162_rn(xr[2 * p] * inv, xr[2 * p + 1] * inv);
            *reinterpret_cast<__nv_bfloat162*>(g_zh + r * ND + 2 * p) = v;
        }
    } else {
        const int N1 = NH * 2 * ND;
        int base = (bx - 128) * 4096 + threadIdx.x * 4;
#pragma unroll
        for (int q = 0; q < 4; q++) {
            int off = base + q * 1024;
            const float* src;
            __nv_bfloat16* dst;
            int o;
            if (off < N1) { src = W1; dst = g_W1h; o = off; }
            else          { src = W2; dst = g_W2h; o = off - N1; }
            float4 v = *reinterpret_cast<const float4*>(src + o);
            *reinterpret_cast<__nv_bfloat162*>(dst + o)     = __floats2bfloat162_rn(v.x, v.y);
            *reinterpret_cast<__nv_bfloat162*>(dst + o + 2) = __floats2bfloat162_rn(v.z, v.w);
        }
    }
}

// ================= kernel B: featw-split (bx<80) | contrast (bx>=80) =======
constexpr int LZA = 776;
constexpr int LZB = 776;
constexpr int LSS = 68;
constexpr int B_ZB = 16 * LZA * 2;                 // 24832
constexpr int B_S0 = B_ZB + 64 * LZB * 2;          // 124160
constexpr int B_S1 = B_S0 + 16 * LSS * 4;          // 128512
constexpr int B_SMEM = B_S1 + 16 * LSS * 4;        // 132864

__global__ void __launch_bounds__(256, 1) k_mid() {
    extern __shared__ __align__(16) char dyn[];
    __nv_bfloat16* za = reinterpret_cast<__nv_bfloat16*>(dyn);
    const int tid = threadIdx.x;
    const int w = tid >> 5, lane = tid & 31;

    if (blockIdx.x < 80) {
        const int t = blockIdx.x;
        const bool isA = t < 16;
        const int rbase = (isA ? (t >> 1) : ((t - 16) >> 1)) * 16;
        const int colh = t & 1;
        const int off = isA ? 0 : ND;

        for (int c = tid; c < 16 * (ND / 8); c += 256) {
            int r = c / (ND / 8), d8 = c % (ND / 8);
            *reinterpret_cast<uint4*>(za + r * LZA + d8 * 8) =
                *reinterpret_cast<const uint4*>(g_zh + (rbase + r) * ND + d8 * 8);
        }
        __syncthreads();

        const int h = colh * 128 + w * 16;
        wmma::fragment<wmma::accumulator, 16, 16, 16, float> ce, co;
        wmma::fill_fragment(ce, 0.f);
        wmma::fill_fragment(co, 0.f);
#pragma unroll 4
        for (int kc = 0; kc < ND / 16; kc += 2) {
            wmma::fragment<wmma::matrix_a, 16, 16, 16, __nv_bfloat16, wmma::row_major> ae, ao;
            wmma::fragment<wmma::matrix_b, 16, 16, 16, __nv_bfloat16, wmma::col_major> be, bo;
            wmma::load_matrix_sync(ae, za + kc * 16, LZA);
            wmma::load_matrix_sync(ao, za + (kc + 1) * 16, LZA);
            wmma::load_matrix_sync(be, g_W1h + h * (2 * ND) + off + kc * 16, 2 * ND);
            wmma::load_matrix_sync(bo, g_W1h + h * (2 * ND) + off + (kc + 1) * 16, 2 * ND);
            wmma::mma_sync(ce, ae, be, ce);
            wmma::mma_sync(co, ao, bo, co);
        }
#pragma unroll
        for (int e = 0; e < ce.num_elements; e++) ce.x[e] += co.x[e];

        if (isA) {
            wmma::store_matrix_sync(g_A + rbase * NH + h, ce, NH, wmma::mem_row_major);
        } else {
            float* cbuf = reinterpret_cast<float*>(dyn);
            __syncthreads();
            wmma::store_matrix_sync(cbuf + w * 16, ce, 132, wmma::mem_row_major);
            __syncthreads();
            for (int c = tid; c < 16 * 64; c += 256) {
                int r = c >> 6, p = c & 63;
                __nv_bfloat162 v = __floats2bfloat162_rn(cbuf[r * 132 + 2 * p],
                                                         cbuf[r * 132 + 2 * p + 1]);
                *reinterpret_cast<__nv_bfloat162*>(g_Bfh + (rbase + r) * NH + colh * 128 + 2 * p) = v;
            }
        }
    } else {
        const int vb = blockIdx.x - 80;
        const int bx = vb >> 3;
        const int by = vb & 7;
        const int ibase = bx * 16;
        const int kbase = by * 64;

        __nv_bfloat16* zb = reinterpret_cast<__nv_bfloat16*>(dyn + B_ZB);
        float* S0 = reinterpret_cast<float*>(dyn + B_S0);
        float* S1 = reinterpret_cast<float*>(dyn + B_S1);

        for (int c = tid; c < 16 * (ND / 8); c += 256) {
            int r = c / (ND / 8), d8 = c % (ND / 8);
            *reinterpret_cast<uint4*>(za + r * LZA + d8 * 8) =
                *reinterpret_cast<const uint4*>(g_zh + (ibase + r) * ND + d8 * 8);
        }
        for (int c = tid; c < 64 * (ND / 8); c += 256) {
            int r = c / (ND / 8), d8 = c % (ND / 8);
            *reinterpret_cast<uint4*>(zb + r * LZB + d8 * 8) =
                *reinterpret_cast<const uint4*>(g_zh + (kbase + r) * ND + d8 * 8);
        }
        __syncthreads();

        const int wn = w & 3;
        const int wd = w >> 2;
        const int kcol = wn * 16;
        const int d0 = wd * 384;

        wmma::fragment<wmma::accumulator, 16, 16, 16, float> cf0, cf1;
        wmma::fill_fragment(cf0, 0.f);
        wmma::fill_fragment(cf1, 0.f);
#pragma unroll 4
        for (int kc = 0; kc < 24; kc += 2) {
            wmma::fragment<wmma::matrix_a, 16, 16, 16, __nv_bfloat16, wmma::row_major> a0, a1;
            wmma::fragment<wmma::matrix_b, 16, 16, 16, __nv_bfloat16, wmma::col_major> b0, b1;
            wmma::load_matrix_sync(a0, za + d0 + kc * 16, LZA);
            wmma::load_matrix_sync(b0, zb + kcol * LZB + d0 + kc * 16, LZB);
            wmma::load_matrix_sync(a1, za + d0 + (kc + 1) * 16, LZA);
            wmma::load_matrix_sync(b1, zb + kcol * LZB + d0 + (kc + 1) * 16, LZB);
            wmma::mma_sync(cf0, a0, b0, cf0);
            wmma::mma_sync(cf1, a1, b1, cf1);
        }
#pragma unroll
        for (int e = 0; e < cf0.num_elements; e++) cf0.x[e] += cf1.x[e];
        wmma::store_matrix_sync((wd ? S1 : S0) + kcol, cf0, LSS, wmma::mem_row_major);
        __syncthreads();

#pragma unroll
        for (int rr = 2 * w; rr <= 2 * w + 1; rr++) {
            int i = ibase + rr;
            float dacc = 0.f, pacc = 0.f;
#pragma unroll
            for (int cc = 0; cc < 2; cc++) {
                int c = lane + cc * 32;
                int k = kbase + c;
                float s = S0[rr * LSS + c] + S1[rr * LSS + c];
                if (k != i) dacc += expf(TAU_INV * s);
                if (k > i && k < NQ) pacc += s;
            }
#pragma unroll
            for (int o = 16; o; o >>= 1) {
                dacc += __shfl_down_sync(0xffffffffu, dacc, o);
                pacc += __shfl_down_sync(0xffffffffu, pacc, o);
            }
            if (lane == 0) {
                g_denomp[i * 8 + by] = dacc;
                g_pairp[i * 8 + by] = pacc;
            }
        }
    }
}

// ================= kernel C: pair MLP (tcgen05, Bf in regs) ================
constexpr int U_SZ  = 196608;
constexpr int P_ASH = U_SZ;                 // 2048
constexpr int P_B2S = P_ASH + 2048;         // 1024
constexpr int P_W3S = P_B2S + 1024;         // 1024
constexpr int P_RR  = P_W3S + 1024;         // 1024
constexpr int P_RED = P_RR + 1024;          // 2048 (4 x 128 partials)
constexpr int P_TM  = P_RED + 2048;         // 16
constexpr int P_MB  = P_TM + 16;            // 32 (two mbarriers)
constexpr int P_SMEM = P_MB + 32;           // 205856

#if defined(__CUDA_ARCH_FEAT_SM103_ALL)
__device__ __forceinline__ uint32_t smem_u32(const void* p) {
    uint32_t a;
    asm("{ .reg .u64 t; cvta.to.shared.u64 t, %1; cvt.u32.u64 %0, t; }" : "=r"(a) : "l"(p));
    return a;
}
__device__ __forceinline__ uint32_t elect_one() {
    uint32_t p;
    asm volatile("{\n\t.reg .pred p;\n\telect.sync _|p, 0xFFFFFFFF;\n\tselp.b32 %0, 1, 0, p;\n\t}" : "=r"(p));
    return p;
}
#define MBAR_INIT(a, n) asm volatile("mbarrier.init.shared.b64 [%0], %1;" :: "r"(a), "r"(n) : "memory")
#define MBAR_WAIT(a, ph) do { \
    uint32_t _m = (a), _p = (ph), _d; \
    asm volatile("{\n\t.reg .pred p;\n\tmbarrier.try_wait.parity.acquire.cta.shared::cta.b64 p, [%1], %2;\n\tselp.b32 %0, 1, 0, p;\n\t}" \
        : "=r"(_d) : "r"(_m), "r"(_p) : "memory"); \
    if (!_d) { \
        asm volatile("{\n\t.reg .pred P1;\n\tWL_%=:\n\tmbarrier.try_wait.parity.acquire.cta.shared::cta.b64 P1, [%0], %1, 0x989680;\n\t@P1 bra.uni WD_%=;\n\tbra.uni WL_%=;\n\tWD_%=:\n\t}" \
            :: "r"(_m), "r"(_p) : "memory"); \
    } } while (0)
#define TC_ALLOC(sa, n)  asm volatile("tcgen05.alloc.cta_group::1.sync.aligned.shared::cta.b32 [%0], %1;" :: "r"(sa), "r"(n) : "memory")
#define TC_RELINQ()      asm volatile("tcgen05.relinquish_alloc_permit.cta_group::1.sync.aligned;")
#define TC_DEALLOC(t, n) asm volatile("tcgen05.dealloc.cta_group::1.sync.aligned.b32 %0, %1;" :: "r"(t), "r"(n))
#define TC_COMMIT(mb)    asm volatile("tcgen05.commit.cta_group::1.mbarrier::arrive::one.shared::cluster.b64 [%0];" :: "r"(mb) : "memory")
#define TC_WAIT_LD()     asm volatile("tcgen05.wait::ld.sync.aligned;" ::: "memory")
#define TC_FENCE_AFTER() asm volatile("tcgen05.fence::after_thread_sync;" ::: "memory")
#define TC_FENCE_BEFORE() asm volatile("tcgen05.fence::before_thread_sync;" ::: "memory")
#define FENCE_ASYNC()    asm volatile("fence.proxy.async.shared::cta;" ::: "memory")
#define TC_LD_X32(r, ta) \
    asm volatile("tcgen05.ld.sync.aligned.32x32b.x32.b32 " \
        "{%0, %1, %2, %3, %4, %5, %6, %7, %8, %9, %10, %11, %12, %13, %14, %15, " \
        " %16, %17, %18, %19, %20, %21, %22, %23, %24, %25, %26, %27, %28, %29, %30, %31}, [%32];" \
        : "=r"((r)[0]), "=r"((r)[1]), "=r"((r)[2]), "=r"((r)[3]), \
          "=r"((r)[4]), "=r"((r)[5]), "=r"((r)[6]), "=r"((r)[7]), \
          "=r"((r)[8]), "=r"((r)[9]), "=r"((r)[10]), "=r"((r)[11]), \
          "=r"((r)[12]), "=r"((r)[13]), "=r"((r)[14]), "=r"((r)[15]), \
          "=r"((r)[16]), "=r"((r)[17]), "=r"((r)[18]), "=r"((r)[19]), \
          "=r"((r)[20]), "=r"((r)[21]), "=r"((r)[22]), "=r"((r)[23]), \
          "=r"((r)[24]), "=r"((r)[25]), "=r"((r)[26]), "=r"((r)[27]), \
          "=r"((r)[28]), "=r"((r)[29]), "=r"((r)[30]), "=r"((r)[31]) \
        : "r"(ta))
__device__ __forceinline__ void mma_f16_ss_cg1(uint32_t d, uint64_t a, uint64_t b,
                                               uint32_t idesc, bool acc) {
    uint32_t en = acc ? 1u : 0u, zero = 0u;
    asm volatile(
        "{\n\t.reg .pred p;\n\tsetp.ne.u32 p, %5, 0;\n\t"
        "tcgen05.mma.cta_group::1.kind::f16 [%0], %1, %2, %3, {%4, %4, %4, %4}, p;\n\t}"
        :: "r"(d), "l"(a), "l"(b), "r"(idesc), "r"(zero), "r"(en) : "memory");
}
__device__ __forceinline__ uint64_t make_desc(uint32_t addr) {
    const uint64_t base = (uint64_t(2) << 61) | (uint64_t(1) << 46)
                        | (uint64_t(64) << 32) | (uint64_t(1) << 16);
    return base | ((uint64_t)(addr >> 4) & 0x3FFF);
}
__device__ __forceinline__ uint32_t sw128(uint32_t x) { return x ^ ((x >> 3) & 0x70); }
// N=128 half-GEMM idesc: f32 accum, bf16 x bf16, N=128, M=128
constexpr uint32_t IDESC_HALF = (1u << 4) | (1u << 7) | (1u << 10)
                              | (16u << 17) | (8u << 24);
#endif

__global__ void __launch_bounds__(256, 1)
k_pair(const float* __restrict__ b1, const float* __restrict__ b2,
       const float* __restrict__ w3, const float* __restrict__ b3v,
       float* __restrict__ out) {
    extern __shared__ __align__(16) char dyn[];
    __nv_bfloat16* ashh = reinterpret_cast<__nv_bfloat16*>(dyn + P_ASH);
    float* b2s = reinterpret_cast<float*>(dyn + P_B2S);
    float* w3s = reinterpret_cast<float*>(dyn + P_W3S);
    float* rr  = reinterpret_cast<float*>(dyn + P_RR);

    const int ibase = blockIdx.x * 4;
    const int j0 = blockIdx.y * 128;
    const int tid = threadIdx.x;
    const int w = tid >> 5, lane = tid & 31;
    const __nv_bfloat162 zero2 = __floats2bfloat162_rn(0.f, 0.f);
    float bacc = 0.f;

    {
        int h = tid;
        float bb = b1[h];
#pragma unroll
        for (int ii = 0; ii < 4; ii++)
            ashh[ii * 256 + h] = __float2bfloat16(g_A[(ibase + ii) * NH + h] + bb);
        b2s[h] = b2[h];
        w3s[h] = w3[h];
    }

#if defined(__CUDA_ARCH_FEAT_SM103_ALL)
    // ============== tcgen05 path: Bf-in-regs, split-N pipelined ==============
    char* w2s = dyn;                 // swizzled W2, 131072 B
    char* h1s = dyn + 131072;        // swizzled h1, 65536 B
    float* red = reinterpret_cast<float*>(dyn + P_RED);   // [4][128]
    const uint32_t sbase = smem_u32(dyn);

    if (w == 0) { TC_ALLOC(sbase + P_TM, NH); TC_RELINQ(); }
    if (tid == 0) {
        MBAR_INIT(sbase + P_MB, 1);
        MBAR_INIT(sbase + P_MB + 8, 1);
    }

    for (int c = tid; c < 256 * 32; c += 256) {
        int n = c >> 5, g = c & 31;
        uint32_t off = (uint32_t)((n >> 3) * 1024 + (g >> 3) * 32768
                                + (n & 7) * 128 + (g & 7) * 16);
        *reinterpret_cast<uint4*>(w2s + sw128(off)) =
            *reinterpret_cast<const uint4*>(g_W2h + n * NH + g * 8);
    }

    // preload this thread's Bf slice: fixed g = tid&31, j = (tid>>5) + 8k
    const int gfix = tid & 31;
    const int jbase = tid >> 5;
    uint4 bfr[16];
#pragma unroll
    for (int k = 0; k < 16; k++)
        bfr[k] = *reinterpret_cast<const uint4*>(g_Bfh + (j0 + jbase + k * 8) * NH + gfix * 8);
    __syncthreads();   // W2 staged; ashh written

    // preload ash slices for all 4 i's
    uint4 ashr[4];
#pragma unroll
    for (int ii = 0; ii < 4; ii++)
        ashr[ii] = *reinterpret_cast<const uint4*>(ashh + ii * 256 + gfix * 8);

    uint32_t tmem;
    asm volatile("ld.shared.b32 %0, [%1];" : "=r"(tmem) : "r"(sbase + P_TM));

    const uint64_t a_base = make_desc(sbase + 131072);
    const uint64_t b_base = make_desc(sbase);
    const int row = (w & 3) * 32 + lane;   // this lane's pair row (subpartition)
    const int chalf = (w >> 2) * 64;       // this warp's 64-col slice of a half
    // constant part of the swizzled h1 offset for this thread
    const uint32_t hoff0 = (uint32_t)((gfix >> 3) * 16384 + jbase * 128 + (gfix & 7) * 16);

    for (int ii = 0; ii < 4; ii++) {
        const int i = ibase + ii;
        // h1 fill: registers -> swizzled smem, no global traffic
        const __nv_bfloat162* ap = reinterpret_cast<const __nv_bfloat162*>(&ashr[ii]);
#pragma unroll
        for (int k = 0; k < 16; k++) {
            uint4 va = bfr[k];
            __nv_bfloat162* hv = reinterpret_cast<__nv_bfloat162*>(&va);
#pragma unroll
            for (int q = 0; q < 4; q++) hv[q] = __hmax2(__hadd2(hv[q], ap[q]), zero2);
            *reinterpret_cast<uint4*>(h1s + sw128(hoff0 + (uint32_t)k * 1024)) = va;
        }
        FENCE_ASYNC();
        __syncthreads();

        if (w == 0) {
            if (elect_one()) {
#pragma unroll
                for (int ks = 0; ks < 16; ks++) {
                    uint64_t ad = a_base + (uint64_t)((ks >> 2) * 1024 + (ks & 3) * 2);
                    uint64_t bd = b_base + (uint64_t)((ks >> 2) * 2048 + (ks & 3) * 2);
                    mma_f16_ss_cg1(tmem, ad, bd, IDESC_HALF, ks > 0);
                }
                TC_COMMIT(sbase + P_MB);
#pragma unroll
                for (int ks = 0; ks < 16; ks++) {
                    uint64_t ad = a_base + (uint64_t)((ks >> 2) * 1024 + (ks & 3) * 2);
                    uint64_t bd = b_base + 1024 + (uint64_t)((ks >> 2) * 2048 + (ks & 3) * 2);
                    mma_f16_ss_cg1(tmem + 128, ad, bd, IDESC_HALF, ks > 0);
                }
                TC_COMMIT(sbase + P_MB + 8);
            }
        }

        // epilogue half 0 (overlaps tensor pipe on half 1): paired LDTM, 1 wait
        MBAR_WAIT(sbase + P_MB, ii & 1);
        TC_FENCE_AFTER();
        {
            uint32_t r0[32], r1[32];
            TC_LD_X32(r0, tmem + chalf);
            TC_LD_X32(r1, tmem + chalf + 32);
            TC_WAIT_LD();
            float s0 = 0.f, s1 = 0.f;
#pragma unroll
            for (int q = 0; q < 32; q++) {
                s0 += fmaxf(__uint_as_float(r0[q]) + b2s[chalf + q], 0.f) * w3s[chalf + q];
                s1 += fmaxf(__uint_as_float(r1[q]) + b2s[chalf + 32 + q], 0.f) * w3s[chalf + 32 + q];
            }
            red[(w >> 2) * 128 + row] = s0 + s1;
        }
        // epilogue half 1
        MBAR_WAIT(sbase + P_MB + 8, ii & 1);
        TC_FENCE_AFTER();
        {
            uint32_t r0[32], r1[32];
            TC_LD_X32(r0, tmem + 128 + chalf);
            TC_LD_X32(r1, tmem + 128 + chalf + 32);
            TC_WAIT_LD();
            float s0 = 0.f, s1 = 0.f;
            const int cb = 128 + chalf;
#pragma unroll
            for (int q = 0; q < 32; q++) {
                s0 += fmaxf(__uint_as_float(r0[q]) + b2s[cb + q], 0.f) * w3s[cb + q];
                s1 += fmaxf(__uint_as_float(r1[q]) + b2s[cb + 32 + q], 0.f) * w3s[cb + 32 + q];
            }
            TC_FENCE_BEFORE();
            red[256 + (w >> 2) * 128 + row] = s0 + s1;
        }
        __syncthreads();

        if (tid < 128) {
            int j = j0 + tid;
            if (j > i) {
                float logit = red[tid] + red[128 + tid] + red[256 + tid]
                            + red[384 + tid] + b3v[0];
                float lab = (j < NM) ? 1.f : 0.f;
                bacc += fmaxf(logit, 0.f) - logit * lab + log1pf(expf(-fabsf(logit)));
            }
        }
        __syncthreads();
    }
    if (w == 0) TC_DEALLOC(tmem, NH);

#else
    // ============== wmma fallback path (compute_103 PTX) ==============
    constexpr int LDH = 264;
    __nv_bfloat16* h1a = reinterpret_cast<__nv_bfloat16*>(dyn);
    __nv_bfloat16* h1b = reinterpret_cast<__nv_bfloat16*>(dyn + 67584);
    float* cscr = reinterpret_cast<float*>(dyn + 135168);
    float* part = reinterpret_cast<float*>(dyn + 151552);
    const int plocal = lane & 15, half = lane >> 4;
    const int c0 = w * 32;

    wmma::fragment<wmma::matrix_b, 16, 16, 16, __nv_bfloat16, wmma::col_major> bf0[16], bf1[16];
#pragma unroll
    for (int k = 0; k < 16; k++) {
        wmma::load_matrix_sync(bf0[k], g_W2h + c0 * NH + k * 16, NH);
        wmma::load_matrix_sync(bf1[k], g_W2h + (c0 + 16) * NH + k * 16, NH);
    }
    float* cs = cscr + w * 512;

    for (int ip = 0; ip < 2; ip++) {
        const int i0 = ibase + 2 * ip, i1 = i0 + 1;
        __syncthreads();
        const __nv_bfloat16* a0 = ashh + 2 * ip * 256;
        const __nv_bfloat16* a1 = a0 + 256;
        for (int c = tid; c < 128 * 32; c += 256) {
            int j = c >> 5, g = c & 31;
            uint4 bv = *reinterpret_cast<const uint4*>(g_Bfh + (j0 + j) * NH + g * 8);
            const __nv_bfloat162* ap0 = reinterpret_cast<const __nv_bfloat162*>(a0 + g * 8);
            const __nv_bfloat162* ap1 = reinterpret_cast<const __nv_bfloat162*>(a1 + g * 8);
            uint4 va = bv, vb = bv;
            __nv_bfloat162* ha = reinterpret_cast<__nv_bfloat162*>(&va);
            __nv_bfloat162* hb = reinterpret_cast<__nv_bfloat162*>(&vb);
#pragma unroll
            for (int q = 0; q < 4; q++) {
                ha[q] = __hmax2(__hadd2(ha[q], ap0[q]), zero2);
                hb[q] = __hmax2(__hadd2(hb[q], ap1[q]), zero2);
            }
            *reinterpret_cast<uint4*>(h1a + j * LDH + g * 8) = va;
            *reinterpret_cast<uint4*>(h1b + j * LDH + g * 8) = vb;
        }
        __syncthreads();

        for (int mt = 0; mt < 8; mt++) {
            wmma::fragment<wmma::accumulator, 16, 16, 16, float> acc00, acc01, acc10, acc11;
            wmma::fill_fragment(acc00, 0.f); wmma::fill_fragment(acc01, 0.f);
            wmma::fill_fragment(acc10, 0.f); wmma::fill_fragment(acc11, 0.f);
#pragma unroll
            for (int k = 0; k < 16; k++) {
                wmma::fragment<wmma::matrix_a, 16, 16, 16, __nv_bfloat16, wmma::row_major> afa, afb;
                wmma::load_matrix_sync(afa, h1a + mt * 16 * LDH + k * 16, LDH);
                wmma::load_matrix_sync(afb, h1b + mt * 16 * LDH + k * 16, LDH);
                wmma::mma_sync(acc00, afa, bf0[k], acc00);
                wmma::mma_sync(acc01, afa, bf1[k], acc01);
                wmma::mma_sync(acc10, afb, bf0[k], acc10);
                wmma::mma_sync(acc11, afb, bf1[k], acc11);
            }
            wmma::store_matrix_sync(cs, acc00, 16, wmma::mem_row_major);
            wmma::store_matrix_sync(cs + 256, acc01, 16, wmma::mem_row_major);
            __syncwarp();
            {
                const float* cp = cs + half * 256 + plocal * 16;
                const int cb = c0 + half * 16;
                float s = 0.f;
#pragma unroll
                for (int q = 0; q < 16; q++)
                    s += fmaxf(cp[q] + b2s[cb + q], 0.f) * w3s[cb + q];
                s += __shfl_down_sync(0xffffffffu, s, 16);
                if (half == 0) part[(mt * 16 + plocal) * 8 + w] = s;
            }
            __syncwarp();
            wmma::store_matrix_sync(cs, acc10, 16, wmma::mem_row_major);
            wmma::store_matrix_sync(cs + 256, acc11, 16, wmma::mem_row_major);
            __syncwarp();
            {
                const float* cp = cs + half * 256 + plocal * 16;
                const int cb = c0 + half * 16;
                float s = 0.f;
#pragma unroll
                for (int q = 0; q < 16; q++)
                    s += fmaxf(cp[q] + b2s[cb + q], 0.f) * w3s[cb + q];
                s += __shfl_down_sync(0xffffffffu, s, 16);
                if (half == 0) part[1024 + (mt * 16 + plocal) * 8 + w] = s;
            }
            __syncwarp();
        }
        __syncthreads();

        if (tid < 128) {
            int j = j0 + tid;
            float l0 = b3v[0], l1 = l0;
#pragma unroll
            for (int q = 0; q < 8; q++) { l0 += part[tid * 8 + q]; l1 += part[1024 + tid * 8 + q]; }
            if (j > i0) {
                float lab = (j < NM) ? 1.f : 0.f;
                bacc += fmaxf(l0, 0.f) - l0 * lab + log1pf(expf(-fabsf(l0)));
            }
            if (j > i1) {
                float lab = (j < NM) ? 1.f : 0.f;
                bacc += fmaxf(l1, 0.f) - l1 * lab + log1pf(expf(-fabsf(l1)));
            }
        }
    }
#endif
    __syncthreads();

    // block reduce bacc
    rr[tid] = bacc;
    __syncthreads();
    for (int st = 128; st > 0; st >>= 1) {
        if (tid < st) rr[tid] += rr[tid + st];
        __syncthreads();
    }
    __shared__ bool isLast;
    if (tid == 0) {
        g_bcep[blockIdx.y * 32 + blockIdx.x] = rr[0];
        __threadfence();
        unsigned v = atomicAdd(&g_ctr, 1u);
        isLast = (v == 127u);
    }
    __syncthreads();
    if (!isLast) return;

    // ----- final reduce (last block, deterministic order) -----
    float b = (tid < 128) ? g_bcep[tid] : 0.f;
    rr[tid] = b;
    __syncthreads();
    for (int st = 128; st > 0; st >>= 1) {
        if (tid < st) rr[tid] += rr[tid + st];
        __syncthreads();
    }
    float bsum = rr[0];
    __syncthreads();

    float c = 0.f;
    if (tid < NQ) {
        int i = tid;
        float den = 0.f, pr = 0.f;
#pragma unroll
        for (int q = 0; q < 8; q++) {
            den += g_denomp[i * 8 + q];
            pr += g_pairp[i * 8 + q];
        }
        c = (float)(NQ - 1 - i) * logf(den) - TAU_INV * pr;
    }
    rr[tid] = c;
    __syncthreads();
    for (int st = 128; st > 0; st >>= 1) {
        if (tid < st) rr[tid] += rr[tid + st];
        __syncthreads();
    }
    if (tid == 0) {
        float closs = (-2.0f * (float)(NQ - 1) / (float)NQ) * rr[0];
        out[0] = closs + bsum / PCOUNT;
    }
}

// ---------------- launch ----------------
extern "C" void kernel_launch(void* const* d_in, const int* in_sizes, int n_in,
                              void* d_out, int out_size) {
    const float* emb = (const float*)d_in[0];
    const float* W1  = (const float*)d_in[1];
    const float* b1  = (const float*)d_in[2];
    const float* W2  = (const float*)d_in[3];
    const float* b2  = (const float*)d_in[4];
    const float* W3  = (const float*)d_in[5];
    const float* b3  = (const float*)d_in[6];

    cudaFuncSetAttribute(k_mid, cudaFuncAttributeMaxDynamicSharedMemorySize, B_SMEM);
    cudaFuncSetAttribute(k_pair, cudaFuncAttributeMaxDynamicSharedMemorySize, P_SMEM);

    k_prep<<<128 + 112, 256>>>(emb, W1, W2);
    k_mid<<<80 + 64, 256, B_SMEM>>>();
    k_pair<<<dim3(32, 4), 256, P_SMEM>>>(b1, b2, W3, b3, (float*)d_out);
}

// round 17
// speedup vs baseline: 1.3154x; 1.0010x over previous
#include <cuda_runtime.h>
#include <cuda_bf16.h>
#include <mma.h>
#include <cstdint>

using namespace nvcuda;

constexpr int NB = 512;   // batch B
constexpr int ND = 768;   // D
constexpr int NH = 256;   // H
constexpr int NQ = 128;   // n = B/4
constexpr int NM = 256;   // m = B/2
constexpr float TAU_INV = 2.0f;
constexpr float PCOUNT = 57280.0f;

// ---------------- scratch ----------------
__device__ __nv_bfloat16 g_zh[NB * ND];
__device__ __nv_bfloat16 g_W1h[NH * 2 * ND];
__device__ __nv_bfloat16 g_W2h[NH * NH];
__device__ float g_A[NQ * NH];
__device__ __nv_bfloat16 g_Bfh[NB * NH];
__device__ float g_denomp[NQ * 8];
__device__ float g_pairp[NQ * 8];
__device__ float g_bcep[128];
__device__ unsigned g_ctr;

// ================= kernel A: norm (bx<128) | W1/W2 convert =================
__global__ void k_prep(const float* __restrict__ x,
                       const float* __restrict__ W1, const float* __restrict__ W2) {
    int bx = blockIdx.x;
    if (bx == 0 && threadIdx.x == 0) g_ctr = 0;
    if (bx < 128) {
        __shared__ float sm[8];
        const int w = threadIdx.x >> 5, lane = threadIdx.x & 31;
        const int r = bx * 4 + (w >> 1);
        const int hoff = (w & 1) * 384;
        const float* xr = x + r * ND;
        float s = 0.f;
#pragma unroll
        for (int q = 0; q < 12; q++) { float v = xr[hoff + lane + q * 32]; s += v * v; }
#pragma unroll
        for (int o = 16; o; o >>= 1) s += __shfl_down_sync(0xffffffffu, s, o);
        if (lane == 0) sm[w] = s;
        __syncthreads();
        float inv = 1.0f / fmaxf(sqrtf(sm[w & ~1] + sm[(w & ~1) + 1]), 1e-12f);
        const int poff = (w & 1) * 192;
#pragma unroll
        for (int q = 0; q < 6; q++) {
            int p = poff + lane + q * 32;
            __nv_bfloat162 v = __floats2bfloat162_rn(xr[2 * p] * inv, xr[2 * p + 1] * inv);
            *reinterpret_cast<__nv_bfloat162*>(g_zh + r * ND + 2 * p) = v;
        }
    } else {
        const int N1 = NH * 2 * ND;
        int base = (bx - 128) * 4096 + threadIdx.x * 4;
#pragma unroll
        for (int q = 0; q < 4; q++) {
            int off = base + q * 1024;
            const float* src;
            __nv_bfloat16* dst;
            int o;
            if (off < N1) { src = W1; dst = g_W1h; o = off; }
            else          { src = W2; dst = g_W2h; o = off - N1; }
            float4 v = *reinterpret_cast<const float4*>(src + o);
            *reinterpret_cast<__nv_bfloat162*>(dst + o)     = __floats2bfloat162_rn(v.x, v.y);
            *reinterpret_cast<__nv_bfloat162*>(dst + o + 2) = __floats2bfloat162_rn(v.z, v.w);
        }
    }
}

// ================= kernel B: featw-split (bx<80) | contrast (bx>=80) =======
constexpr int LZA = 776;
constexpr int LZB = 776;
constexpr int LSS = 68;
constexpr int B_ZB = 16 * LZA * 2;                 // 24832
constexpr int B_S0 = B_ZB + 64 * LZB * 2;          // 124160
constexpr int B_S1 = B_S0 + 16 * LSS * 4;          // 128512
constexpr int B_SMEM = B_S1 + 16 * LSS * 4;        // 132864

__global__ void __launch_bounds__(256, 1) k_mid() {
    extern __shared__ __align__(16) char dyn[];
    __nv_bfloat16* za = reinterpret_cast<__nv_bfloat16*>(dyn);
    const int tid = threadIdx.x;
    const int w = tid >> 5, lane = tid & 31;

    if (blockIdx.x < 80) {
        const int t = blockIdx.x;
        const bool isA = t < 16;
        const int rbase = (isA ? (t >> 1) : ((t - 16) >> 1)) * 16;
        const int colh = t & 1;
        const int off = isA ? 0 : ND;

        for (int c = tid; c < 16 * (ND / 8); c += 256) {
            int r = c / (ND / 8), d8 = c % (ND / 8);
            *reinterpret_cast<uint4*>(za + r * LZA + d8 * 8) =
                *reinterpret_cast<const uint4*>(g_zh + (rbase + r) * ND + d8 * 8);
        }
        __syncthreads();

        const int h = colh * 128 + w * 16;
        wmma::fragment<wmma::accumulator, 16, 16, 16, float> ce, co;
        wmma::fill_fragment(ce, 0.f);
        wmma::fill_fragment(co, 0.f);
#pragma unroll 4
        for (int kc = 0; kc < ND / 16; kc += 2) {
            wmma::fragment<wmma::matrix_a, 16, 16, 16, __nv_bfloat16, wmma::row_major> ae, ao;
            wmma::fragment<wmma::matrix_b, 16, 16, 16, __nv_bfloat16, wmma::col_major> be, bo;
            wmma::load_matrix_sync(ae, za + kc * 16, LZA);
            wmma::load_matrix_sync(ao, za + (kc + 1) * 16, LZA);
            wmma::load_matrix_sync(be, g_W1h + h * (2 * ND) + off + kc * 16, 2 * ND);
            wmma::load_matrix_sync(bo, g_W1h + h * (2 * ND) + off + (kc + 1) * 16, 2 * ND);
            wmma::mma_sync(ce, ae, be, ce);
            wmma::mma_sync(co, ao, bo, co);
        }
#pragma unroll
        for (int e = 0; e < ce.num_elements; e++) ce.x[e] += co.x[e];

        if (isA) {
            wmma::store_matrix_sync(g_A + rbase * NH + h, ce, NH, wmma::mem_row_major);
        } else {
            float* cbuf = reinterpret_cast<float*>(dyn);
            __syncthreads();
            wmma::store_matrix_sync(cbuf + w * 16, ce, 132, wmma::mem_row_major);
            __syncthreads();
            for (int c = tid; c < 16 * 64; c += 256) {
                int r = c >> 6, p = c & 63;
                __nv_bfloat162 v = __floats2bfloat162_rn(cbuf[r * 132 + 2 * p],
                                                         cbuf[r * 132 + 2 * p + 1]);
                *reinterpret_cast<__nv_bfloat162*>(g_Bfh + (rbase + r) * NH + colh * 128 + 2 * p) = v;
            }
        }
    } else {
        const int vb = blockIdx.x - 80;
        const int bx = vb >> 3;
        const int by = vb & 7;
        const int ibase = bx * 16;
        const int kbase = by * 64;

        __nv_bfloat16* zb = reinterpret_cast<__nv_bfloat16*>(dyn + B_ZB);
        float* S0 = reinterpret_cast<float*>(dyn + B_S0);
        float* S1 = reinterpret_cast<float*>(dyn + B_S1);

        for (int c = tid; c < 16 * (ND / 8); c += 256) {
            int r = c / (ND / 8), d8 = c % (ND / 8);
            *reinterpret_cast<uint4*>(za + r * LZA + d8 * 8) =
                *reinterpret_cast<const uint4*>(g_zh + (ibase + r) * ND + d8 * 8);
        }
        for (int c = tid; c < 64 * (ND / 8); c += 256) {
            int r = c / (ND / 8), d8 = c % (ND / 8);
            *reinterpret_cast<uint4*>(zb + r * LZB + d8 * 8) =
                *reinterpret_cast<const uint4*>(g_zh + (kbase + r) * ND + d8 * 8);
        }
        __syncthreads();

        const int wn = w & 3;
        const int wd = w >> 2;
        const int kcol = wn * 16;
        const int d0 = wd * 384;

        wmma::fragment<wmma::accumulator, 16, 16, 16, float> cf0, cf1;
        wmma::fill_fragment(cf0, 0.f);
        wmma::fill_fragment(cf1, 0.f);
#pragma unroll 4
        for (int kc = 0; kc < 24; kc += 2) {
            wmma::fragment<wmma::matrix_a, 16, 16, 16, __nv_bfloat16, wmma::row_major> a0, a1;
            wmma::fragment<wmma::matrix_b, 16, 16, 16, __nv_bfloat16, wmma::col_major> b0, b1;
            wmma::load_matrix_sync(a0, za + d0 + kc * 16, LZA);
            wmma::load_matrix_sync(b0, zb + kcol * LZB + d0 + kc * 16, LZB);
            wmma::load_matrix_sync(a1, za + d0 + (kc + 1) * 16, LZA);
            wmma::load_matrix_sync(b1, zb + kcol * LZB + d0 + (kc + 1) * 16, LZB);
            wmma::mma_sync(cf0, a0, b0, cf0);
            wmma::mma_sync(cf1, a1, b1, cf1);
        }
#pragma unroll
        for (int e = 0; e < cf0.num_elements; e++) cf0.x[e] += cf1.x[e];
        wmma::store_matrix_sync((wd ? S1 : S0) + kcol, cf0, LSS, wmma::mem_row_major);
        __syncthreads();

#pragma unroll
        for (int rr = 2 * w; rr <= 2 * w + 1; rr++) {
            int i = ibase + rr;
            float dacc = 0.f, pacc = 0.f;
#pragma unroll
            for (int cc = 0; cc < 2; cc++) {
                int c = lane + cc * 32;
                int k = kbase + c;
                float s = S0[rr * LSS + c] + S1[rr * LSS + c];
                if (k != i) dacc += expf(TAU_INV * s);
                if (k > i && k < NQ) pacc += s;
            }
#pragma unroll
            for (int o = 16; o; o >>= 1) {
                dacc += __shfl_down_sync(0xffffffffu, dacc, o);
                pacc += __shfl_down_sync(0xffffffffu, pacc, o);
            }
            if (lane == 0) {
                g_denomp[i * 8 + by] = dacc;
                g_pairp[i * 8 + by] = pacc;
            }
        }
    }
}

// ================= kernel C: pair MLP (tcgen05, pipelined) =================
constexpr int U_SZ  = 196608;
constexpr int P_ASH = U_SZ;                 // 2048
constexpr int P_BW  = P_ASH + 2048;         // 2048 (256 float2: b2,w3)
constexpr int P_RR  = P_BW + 2048;          // 1024
constexpr int P_RED = P_RR + 1024;          // 2048 (4 x 128 partials)
constexpr int P_TM  = P_RED + 2048;         // 16
constexpr int P_MB  = P_TM + 16;            // 32 (two mbarriers)
constexpr int P_SMEM = P_MB + 32;           // 205856

#if defined(__CUDA_ARCH_FEAT_SM103_ALL)
__device__ __forceinline__ uint32_t smem_u32(const void* p) {
    uint32_t a;
    asm("{ .reg .u64 t; cvta.to.shared.u64 t, %1; cvt.u32.u64 %0, t; }" : "=r"(a) : "l"(p));
    return a;
}
__device__ __forceinline__ uint32_t elect_one() {
    uint32_t p;
    asm volatile("{\n\t.reg .pred p;\n\telect.sync _|p, 0xFFFFFFFF;\n\tselp.b32 %0, 1, 0, p;\n\t}" : "=r"(p));
    return p;
}
#define MBAR_INIT(a, n) asm volatile("mbarrier.init.shared.b64 [%0], %1;" :: "r"(a), "r"(n) : "memory")
#define MBAR_WAIT(a, ph) do { \
    uint32_t _m = (a), _p = (ph), _d; \
    asm volatile("{\n\t.reg .pred p;\n\tmbarrier.try_wait.parity.acquire.cta.shared::cta.b64 p, [%1], %2;\n\tselp.b32 %0, 1, 0, p;\n\t}" \
        : "=r"(_d) : "r"(_m), "r"(_p) : "memory"); \
    if (!_d) { \
        asm volatile("{\n\t.reg .pred P1;\n\tWL_%=:\n\tmbarrier.try_wait.parity.acquire.cta.shared::cta.b64 P1, [%0], %1, 0x989680;\n\t@P1 bra.uni WD_%=;\n\tbra.uni WL_%=;\n\tWD_%=:\n\t}" \
            :: "r"(_m), "r"(_p) : "memory"); \
    } } while (0)
#define TC_ALLOC(sa, n)  asm volatile("tcgen05.alloc.cta_group::1.sync.aligned.shared::cta.b32 [%0], %1;" :: "r"(sa), "r"(n) : "memory")
#define TC_RELINQ()      asm volatile("tcgen05.relinquish_alloc_permit.cta_group::1.sync.aligned;")
#define TC_DEALLOC(t, n) asm volatile("tcgen05.dealloc.cta_group::1.sync.aligned.b32 %0, %1;" :: "r"(t), "r"(n))
#define TC_COMMIT(mb)    asm volatile("tcgen05.commit.cta_group::1.mbarrier::arrive::one.shared::cluster.b64 [%0];" :: "r"(mb) : "memory")
#define TC_WAIT_LD()     asm volatile("tcgen05.wait::ld.sync.aligned;" ::: "memory")
#define TC_FENCE_AFTER() asm volatile("tcgen05.fence::after_thread_sync;" ::: "memory")
#define TC_FENCE_BEFORE() asm volatile("tcgen05.fence::before_thread_sync;" ::: "memory")
#define FENCE_ASYNC()    asm volatile("fence.proxy.async.shared::cta;" ::: "memory")
#define TC_LD_X32(r, ta) \
    asm volatile("tcgen05.ld.sync.aligned.32x32b.x32.b32 " \
        "{%0, %1, %2, %3, %4, %5, %6, %7, %8, %9, %10, %11, %12, %13, %14, %15, " \
        " %16, %17, %18, %19, %20, %21, %22, %23, %24, %25, %26, %27, %28, %29, %30, %31}, [%32];" \
        : "=r"((r)[0]), "=r"((r)[1]), "=r"((r)[2]), "=r"((r)[3]), \
          "=r"((r)[4]), "=r"((r)[5]), "=r"((r)[6]), "=r"((r)[7]), \
          "=r"((r)[8]), "=r"((r)[9]), "=r"((r)[10]), "=r"((r)[11]), \
          "=r"((r)[12]), "=r"((r)[13]), "=r"((r)[14]), "=r"((r)[15]), \
          "=r"((r)[16]), "=r"((r)[17]), "=r"((r)[18]), "=r"((r)[19]), \
          "=r"((r)[20]), "=r"((r)[21]), "=r"((r)[22]), "=r"((r)[23]), \
          "=r"((r)[24]), "=r"((r)[25]), "=r"((r)[26]), "=r"((r)[27]), \
          "=r"((r)[28]), "=r"((r)[29]), "=r"((r)[30]), "=r"((r)[31]) \
        : "r"(ta))
__device__ __forceinline__ void mma_f16_ss_cg1(uint32_t d, uint64_t a, uint64_t b,
                                               uint32_t idesc, bool acc) {
    uint32_t en = acc ? 1u : 0u, zero = 0u;
    asm volatile(
        "{\n\t.reg .pred p;\n\tsetp.ne.u32 p, %5, 0;\n\t"
        "tcgen05.mma.cta_group::1.kind::f16 [%0], %1, %2, %3, {%4, %4, %4, %4}, p;\n\t}"
        :: "r"(d), "l"(a), "l"(b), "r"(idesc), "r"(zero), "r"(en) : "memory");
}
__device__ __forceinline__ uint64_t make_desc(uint32_t addr) {
    const uint64_t base = (uint64_t(2) << 61) | (uint64_t(1) << 46)
                        | (uint64_t(64) << 32) | (uint64_t(1) << 16);
    return base | ((uint64_t)(addr >> 4) & 0x3FFF);
}
__device__ __forceinline__ uint32_t sw128(uint32_t x) { return x ^ ((x >> 3) & 0x70); }
// N=128 half-GEMM idesc: f32 accum, bf16 x bf16, N=128, M=128
constexpr uint32_t IDESC_HALF = (1u << 4) | (1u << 7) | (1u << 10)
                              | (16u << 17) | (8u << 24);
#endif

__global__ void __launch_bounds__(256, 1)
k_pair(const float* __restrict__ b1, const float* __restrict__ b2,
       const float* __restrict__ w3, const float* __restrict__ b3v,
       float* __restrict__ out) {
    extern __shared__ __align__(16) char dyn[];
    __nv_bfloat16* ashh = reinterpret_cast<__nv_bfloat16*>(dyn + P_ASH);
    float2* b2w3 = reinterpret_cast<float2*>(dyn + P_BW);
    float* rr  = reinterpret_cast<float*>(dyn + P_RR);

    const int ibase = blockIdx.x * 4;
    const int j0 = blockIdx.y * 128;
    const int tid = threadIdx.x;
    const int w = tid >> 5, lane = tid & 31;
    const __nv_bfloat162 zero2 = __floats2bfloat162_rn(0.f, 0.f);
    float bacc = 0.f;

    {
        int h = tid;
        float bb = b1[h];
#pragma unroll
        for (int ii = 0; ii < 4; ii++)
            ashh[ii * 256 + h] = __float2bfloat16(g_A[(ibase + ii) * NH + h] + bb);
        b2w3[h] = make_float2(b2[h], w3[h]);
    }

#if defined(__CUDA_ARCH_FEAT_SM103_ALL)
    // ===== tcgen05 path: Bf-in-regs, split-N, cross-i pipelined =====
    char* w2s = dyn;                 // swizzled W2, 131072 B
    char* h1s = dyn + 131072;        // swizzled h1, 65536 B
    float* red = reinterpret_cast<float*>(dyn + P_RED);   // [4][128]
    const uint32_t sbase = smem_u32(dyn);

    if (w == 0) { TC_ALLOC(sbase + P_TM, NH); TC_RELINQ(); }
    if (tid == 0) {
        MBAR_INIT(sbase + P_MB, 1);
        MBAR_INIT(sbase + P_MB + 8, 1);
    }

    for (int c = tid; c < 256 * 32; c += 256) {
        int n = c >> 5, g = c & 31;
        uint32_t off = (uint32_t)((n >> 3) * 1024 + (g >> 3) * 32768
                                + (n & 7) * 128 + (g & 7) * 16);
        *reinterpret_cast<uint4*>(w2s + sw128(off)) =
            *reinterpret_cast<const uint4*>(g_W2h + n * NH + g * 8);
    }

    // preload this thread's Bf slice: fixed g = tid&31, j = (tid>>5) + 8k
    const int gfix = tid & 31;
    const int jbase = tid >> 5;
    uint4 bfr[16];
#pragma unroll
    for (int k = 0; k < 16; k++)
        bfr[k] = *reinterpret_cast<const uint4*>(g_Bfh + (j0 + jbase + k * 8) * NH + gfix * 8);
    __syncthreads();   // W2 staged; ashh written

    uint4 ashr[4];
#pragma unroll
    for (int ii = 0; ii < 4; ii++)
        ashr[ii] = *reinterpret_cast<const uint4*>(ashh + ii * 256 + gfix * 8);

    uint32_t tmem;
    asm volatile("ld.shared.b32 %0, [%1];" : "=r"(tmem) : "r"(sbase + P_TM));

    const uint64_t a_base = make_desc(sbase + 131072);
    const uint64_t b_base = make_desc(sbase);
    const int row = (w & 3) * 32 + lane;
    const int chalf = (w >> 2) * 64;
    const uint32_t hoff0 = (uint32_t)((gfix >> 3) * 16384 + jbase * 128 + (gfix & 7) * 16);

    // prologue: fill h1(0), issue MMA(0) half0
    {
        const __nv_bfloat162* ap = reinterpret_cast<const __nv_bfloat162*>(&ashr[0]);
#pragma unroll
        for (int k = 0; k < 16; k++) {
            uint4 va = bfr[k];
            __nv_bfloat162* hv = reinterpret_cast<__nv_bfloat162*>(&va);
#pragma unroll
            for (int q = 0; q < 4; q++) hv[q] = __hmax2(__hadd2(hv[q], ap[q]), zero2);
            *reinterpret_cast<uint4*>(h1s + sw128(hoff0 + (uint32_t)k * 1024)) = va;
        }
    }
    FENCE_ASYNC();
    __syncthreads();
    if (w == 0) {
        if (elect_one()) {
#pragma unroll
            for (int ks = 0; ks < 16; ks++) {
                uint64_t ad = a_base + (uint64_t)((ks >> 2) * 1024 + (ks & 3) * 2);
                uint64_t bd = b_base + (uint64_t)((ks >> 2) * 2048 + (ks & 3) * 2);
                mma_f16_ss_cg1(tmem, ad, bd, IDESC_HALF, ks > 0);
            }
            TC_COMMIT(sbase + P_MB);
        }
    }

    for (int ii = 0; ii < 4; ii++) {
        const int i = ibase + ii;
        // issue MMA(ii) half1 (D half1 free: epi half1(ii-1) done before last sync)
        if (w == 0) {
            if (elect_one()) {
#pragma unroll
                for (int ks = 0; ks < 16; ks++) {
                    uint64_t ad = a_base + (uint64_t)((ks >> 2) * 1024 + (ks & 3) * 2);
                    uint64_t bd = b_base + 1024 + (uint64_t)((ks >> 2) * 2048 + (ks & 3) * 2);
                    mma_f16_ss_cg1(tmem + 128, ad, bd, IDESC_HALF, ks > 0);
                }
                TC_COMMIT(sbase + P_MB + 8);
            }
        }

        // epilogue half 0 (overlaps MMA half1)
        MBAR_WAIT(sbase + P_MB, ii & 1);
        TC_FENCE_AFTER();
        {
            uint32_t r0[32], r1[32];
            TC_LD_X32(r0, tmem + chalf);
            TC_LD_X32(r1, tmem + chalf + 32);
            TC_WAIT_LD();
            float s0 = 0.f, s1 = 0.f;
#pragma unroll
            for (int q = 0; q < 32; q++) {
                float2 bw0 = b2w3[chalf + q];
                float2 bw1 = b2w3[chalf + 32 + q];
                s0 = fmaf(fmaxf(__uint_as_float(r0[q]) + bw0.x, 0.f), bw0.y, s0);
                s1 = fmaf(fmaxf(__uint_as_float(r1[q]) + bw1.x, 0.f), bw1.y, s1);
            }
            red[(w >> 2) * 128 + row] = s0 + s1;
        }

        // wait MMA half1 done (last h1 read), then fill h1(ii+1)
        MBAR_WAIT(sbase + P_MB + 8, ii & 1);
        TC_FENCE_AFTER();
        if (ii < 3) {
            const __nv_bfloat162* ap = reinterpret_cast<const __nv_bfloat162*>(&ashr[ii + 1]);
#pragma unroll
            for (int k = 0; k < 16; k++) {
                uint4 va = bfr[k];
                __nv_bfloat162* hv = reinterpret_cast<__nv_bfloat162*>(&va);
#pragma unroll
                for (int q = 0; q < 4; q++) hv[q] = __hmax2(__hadd2(hv[q], ap[q]), zero2);
                *reinterpret_cast<uint4*>(h1s + sw128(hoff0 + (uint32_t)k * 1024)) = va;
            }
            FENCE_ASYNC();
        }

        // epilogue half 1
        {
            uint32_t r0[32], r1[32];
            TC_LD_X32(r0, tmem + 128 + chalf);
            TC_LD_X32(r1, tmem + 128 + chalf + 32);
            TC_WAIT_LD();
            float s0 = 0.f, s1 = 0.f;
            const int cb = 128 + chalf;
#pragma unroll
            for (int q = 0; q < 32; q++) {
                float2 bw0 = b2w3[cb + q];
                float2 bw1 = b2w3[cb + 32 + q];
                s0 = fmaf(fmaxf(__uint_as_float(r0[q]) + bw0.x, 0.f), bw0.y, s0);
                s1 = fmaf(fmaxf(__uint_as_float(r1[q]) + bw1.x, 0.f), bw1.y, s1);
            }
            TC_FENCE_BEFORE();
            red[256 + (w >> 2) * 128 + row] = s0 + s1;
        }
        __syncthreads();   // h1(ii+1) visible; red ready; epi LDTMs done

        // issue MMA(ii+1) half0 (D half0 free: epi half0(ii) completed)
        if (ii < 3 && w == 0) {
            if (elect_one()) {
#pragma unroll
                for (int ks = 0; ks < 16; ks++) {
                    uint64_t ad = a_base + (uint64_t)((ks >> 2) * 1024 + (ks & 3) * 2);
                    uint64_t bd = b_base + (uint64_t)((ks >> 2) * 2048 + (ks & 3) * 2);
                    mma_f16_ss_cg1(tmem, ad, bd, IDESC_HALF, ks > 0);
                }
                TC_COMMIT(sbase + P_MB);
            }
        }

        if (tid < 128) {
            int j = j0 + tid;
            if (j > i) {
                float logit = red[tid] + red[128 + tid] + red[256 + tid]
                            + red[384 + tid] + b3v[0];
                float lab = (j < NM) ? 1.f : 0.f;
                bacc += fmaxf(logit, 0.f) - logit * lab + log1pf(expf(-fabsf(logit)));
            }
        }
        __syncthreads();   // red reads done before next epi writes
    }
    if (w == 0) TC_DEALLOC(tmem, NH);

#else
    // ============== wmma fallback path (compute_103 PTX) ==============
    constexpr int LDH = 264;
    __nv_bfloat16* h1a = reinterpret_cast<__nv_bfloat16*>(dyn);
    __nv_bfloat16* h1b = reinterpret_cast<__nv_bfloat16*>(dyn + 67584);
    float* cscr = reinterpret_cast<float*>(dyn + 135168);
    float* part = reinterpret_cast<float*>(dyn + 151552);
    const int plocal = lane & 15, half = lane >> 4;
    const int c0 = w * 32;

    wmma::fragment<wmma::matrix_b, 16, 16, 16, __nv_bfloat16, wmma::col_major> bf0[16], bf1[16];
#pragma unroll
    for (int k = 0; k < 16; k++) {
        wmma::load_matrix_sync(bf0[k], g_W2h + c0 * NH + k * 16, NH);
        wmma::load_matrix_sync(bf1[k], g_W2h + (c0 + 16) * NH + k * 16, NH);
    }
    float* cs = cscr + w * 512;

    for (int ip = 0; ip < 2; ip++) {
        const int i0 = ibase + 2 * ip, i1 = i0 + 1;
        __syncthreads();
        const __nv_bfloat16* a0 = ashh + 2 * ip * 256;
        const __nv_bfloat16* a1 = a0 + 256;
        for (int c = tid; c < 128 * 32; c += 256) {
            int j = c >> 5, g = c & 31;
            uint4 bv = *reinterpret_cast<const uint4*>(g_Bfh + (j0 + j) * NH + g * 8);
            const __nv_bfloat162* ap0 = reinterpret_cast<const __nv_bfloat162*>(a0 + g * 8);
            const __nv_bfloat162* ap1 = reinterpret_cast<const __nv_bfloat162*>(a1 + g * 8);
            uint4 va = bv, vb = bv;
            __nv_bfloat162* ha = reinterpret_cast<__nv_bfloat162*>(&va);
            __nv_bfloat162* hb = reinterpret_cast<__nv_bfloat162*>(&vb);
#pragma unroll
            for (int q = 0; q < 4; q++) {
                ha[q] = __hmax2(__hadd2(ha[q], ap0[q]), zero2);
                hb[q] = __hmax2(__hadd2(hb[q], ap1[q]), zero2);
            }
            *reinterpret_cast<uint4*>(h1a + j * LDH + g * 8) = va;
            *reinterpret_cast<uint4*>(h1b + j * LDH + g * 8) = vb;
        }
        __syncthreads();

        for (int mt = 0; mt < 8; mt++) {
            wmma::fragment<wmma::accumulator, 16, 16, 16, float> acc00, acc01, acc10, acc11;
            wmma::fill_fragment(acc00, 0.f); wmma::fill_fragment(acc01, 0.f);
            wmma::fill_fragment(acc10, 0.f); wmma::fill_fragment(acc11, 0.f);
#pragma unroll
            for (int k = 0; k < 16; k++) {
                wmma::fragment<wmma::matrix_a, 16, 16, 16, __nv_bfloat16, wmma::row_major> afa, afb;
                wmma::load_matrix_sync(afa, h1a + mt * 16 * LDH + k * 16, LDH);
                wmma::load_matrix_sync(afb, h1b + mt * 16 * LDH + k * 16, LDH);
                wmma::mma_sync(acc00, afa, bf0[k], acc00);
                wmma::mma_sync(acc01, afa, bf1[k], acc01);
                wmma::mma_sync(acc10, afb, bf0[k], acc10);
                wmma::mma_sync(acc11, afb, bf1[k], acc11);
            }
            wmma::store_matrix_sync(cs, acc00, 16, wmma::mem_row_major);
            wmma::store_matrix_sync(cs + 256, acc01, 16, wmma::mem_row_major);
            __syncwarp();
            {
                const float* cp = cs + half * 256 + plocal * 16;
                const int cb = c0 + half * 16;
                float s = 0.f;
#pragma unroll
                for (int q = 0; q < 16; q++) {
                    float2 bw = b2w3[cb + q];
                    s = fmaf(fmaxf(cp[q] + bw.x, 0.f), bw.y, s);
                }
                s += __shfl_down_sync(0xffffffffu, s, 16);
                if (half == 0) part[(mt * 16 + plocal) * 8 + w] = s;
            }
            __syncwarp();
            wmma::store_matrix_sync(cs, acc10, 16, wmma::mem_row_major);
            wmma::store_matrix_sync(cs + 256, acc11, 16, wmma::mem_row_major);
            __syncwarp();
            {
                const float* cp = cs + half * 256 + plocal * 16;
                const int cb = c0 + half * 16;
                float s = 0.f;
#pragma unroll
                for (int q = 0; q < 16; q++) {
                    float2 bw = b2w3[cb + q];
                    s = fmaf(fmaxf(cp[q] + bw.x, 0.f), bw.y, s);
                }
                s += __shfl_down_sync(0xffffffffu, s, 16);
                if (half == 0) part[1024 + (mt * 16 + plocal) * 8 + w] = s;
            }
            __syncwarp();
        }
        __syncthreads();

        if (tid < 128) {
            int j = j0 + tid;
            float l0 = b3v[0], l1 = l0;
#pragma unroll
            for (int q = 0; q < 8; q++) { l0 += part[tid * 8 + q]; l1 += part[1024 + tid * 8 + q]; }
            if (j > i0) {
                float lab = (j < NM) ? 1.f : 0.f;
                bacc += fmaxf(l0, 0.f) - l0 * lab + log1pf(expf(-fabsf(l0)));
            }
            if (j > i1) {
                float lab = (j < NM) ? 1.f : 0.f;
                bacc += fmaxf(l1, 0.f) - l1 * lab + log1pf(expf(-fabsf(l1)));
            }
        }
    }
#endif
    __syncthreads();

    // block reduce bacc
    rr[tid] = bacc;
    __syncthreads();
    for (int st = 128; st > 0; st >>= 1) {
        if (tid < st) rr[tid] += rr[tid + st];
        __syncthreads();
    }
    __shared__ bool isLast;
    if (tid == 0) {
        g_bcep[blockIdx.y * 32 + blockIdx.x] = rr[0];
        __threadfence();
        unsigned v = atomicAdd(&g_ctr, 1u);
        isLast = (v == 127u);
    }
    __syncthreads();
    if (!isLast) return;

    // ----- final reduce (last block, deterministic order) -----
    float b = (tid < 128) ? g_bcep[tid] : 0.f;
    rr[tid] = b;
    __syncthreads();
    for (int st = 128; st > 0; st >>= 1) {
        if (tid < st) rr[tid] += rr[tid + st];
        __syncthreads();
    }
    float bsum = rr[0];
    __syncthreads();

    float c = 0.f;
    if (tid < NQ) {
        int i = tid;
        float den = 0.f, pr = 0.f;
#pragma unroll
        for (int q = 0; q < 8; q++) {
            den += g_denomp[i * 8 + q];
            pr += g_pairp[i * 8 + q];
        }
        c = (float)(NQ - 1 - i) * logf(den) - TAU_INV * pr;
    }
    rr[tid] = c;
    __syncthreads();
    for (int st = 128; st > 0; st >>= 1) {
        if (tid < st) rr[tid] += rr[tid + st];
        __syncthreads();
    }
    if (tid == 0) {
        float closs = (-2.0f * (float)(NQ - 1) / (float)NQ) * rr[0];
        out[0] = closs + bsum / PCOUNT;
    }
}

// ---------------- launch ----------------
extern "C" void kernel_launch(void* const* d_in, const int* in_sizes, int n_in,
                              void* d_out, int out_size) {
    const float* emb = (const float*)d_in[0];
    const float* W1  = (const float*)d_in[1];
    const float* b1  = (const float*)d_in[2];
    const float* W2  = (const float*)d_in[3];
    const float* b2  = (const float*)d_in[4];
    const float* W3  = (const float*)d_in[5];
    const float* b3  = (const float*)d_in[6];

    cudaFuncSetAttribute(k_mid, cudaFuncAttributeMaxDynamicSharedMemorySize, B_SMEM);
    cudaFuncSetAttribute(k_pair, cudaFuncAttributeMaxDynamicSharedMemorySize, P_SMEM);

    k_prep<<<128 + 112, 256>>>(emb, W1, W2);
    k_mid<<<80 + 64, 256, B_SMEM>>>();
    k_pair<<<dim3(32, 4), 256, P_SMEM>>>(b1, b2, W3, b3, (float*)d_out);
}